// round 5
// baseline (speedup 1.0000x reference)
#include <cuda_runtime.h>
#include <cuda_bf16.h>
#include <cstdint>
#include <math.h>

#define DIM   512
#define LBLK  64
#define NHEAD 8
#define KEYS  65
#define BB    2
#define NTOK  32768
#define NBPB  512
#define NBLK  (BB*NBPB)           // 1024
#define MTOK  (BB*NTOK)           // 65536
#define MAUG  (MTOK+NBLK)         // 66560
#define QKVN  (3*DIM)             // 1536
#define GK    512

// ---------------- scratch ----------------------------------------------------
__device__ __nv_bfloat16 g_xh[(size_t)MAUG * DIM];
__device__ __nv_bfloat16 g_xl[(size_t)MAUG * DIM];
__device__ __nv_bfloat16 g_yh[(size_t)MAUG * QKVN];   // split qkv hi
__device__ __nv_bfloat16 g_yl[(size_t)MAUG * QKVN];   // split qkv lo
__device__ __nv_bfloat16 g_aoh[(size_t)MTOK * DIM];
__device__ __nv_bfloat16 g_aol[(size_t)MTOK * DIM];
__device__ __nv_bfloat16 g_qwh[(size_t)QKVN * DIM];
__device__ __nv_bfloat16 g_qwl[(size_t)QKVN * DIM];
__device__ __nv_bfloat16 g_pwh[(size_t)DIM * DIM];
__device__ __nv_bfloat16 g_pwl[(size_t)DIM * DIM];

// ---------------- helpers ----------------------------------------------------
__device__ __forceinline__ uint32_t smem_u32(const void* p) {
    uint32_t a;
    asm("{ .reg .u64 t; cvta.to.shared.u64 t, %1; cvt.u32.u64 %0, t; }"
        : "=r"(a) : "l"(p));
    return a;
}
__device__ __forceinline__ void cp_async16(uint32_t dst, const void* src) {
    asm volatile("cp.async.cg.shared.global [%0], [%1], 16;"
                 :: "r"(dst), "l"(src) : "memory");
}
#define CP_COMMIT() asm volatile("cp.async.commit_group;" ::: "memory")
#define CP_WAIT(n)  asm volatile("cp.async.wait_group %0;" :: "n"(n) : "memory")

__device__ __forceinline__ void ldsm4(uint32_t (&r)[4], uint32_t addr) {
    asm volatile("ldmatrix.sync.aligned.m8n8.x4.shared.b16 {%0,%1,%2,%3}, [%4];"
                 : "=r"(r[0]), "=r"(r[1]), "=r"(r[2]), "=r"(r[3]) : "r"(addr));
}
__device__ __forceinline__ void ldsm4t(uint32_t (&r)[4], uint32_t addr) {
    asm volatile("ldmatrix.sync.aligned.m8n8.x4.trans.shared.b16 {%0,%1,%2,%3}, [%4];"
                 : "=r"(r[0]), "=r"(r[1]), "=r"(r[2]), "=r"(r[3]) : "r"(addr));
}
__device__ __forceinline__ void mma16816(float (&d)[4], const uint32_t (&a)[4],
                                         const uint32_t b0, const uint32_t b1) {
    asm volatile(
        "mma.sync.aligned.m16n8k16.row.col.f32.bf16.bf16.f32 "
        "{%0,%1,%2,%3}, {%4,%5,%6,%7}, {%8,%9}, {%0,%1,%2,%3};"
        : "+f"(d[0]), "+f"(d[1]), "+f"(d[2]), "+f"(d[3])
        : "r"(a[0]), "r"(a[1]), "r"(a[2]), "r"(a[3]), "r"(b0), "r"(b1));
}
__device__ __forceinline__ void split1(float v, __nv_bfloat16& h, __nv_bfloat16& l) {
    h = __float2bfloat16(v);
    l = __float2bfloat16(v - __bfloat162float(h));
}
__device__ __forceinline__ uint32_t pack_bf2(float c0, float c1) {
    uint32_t d;
    asm("cvt.rn.bf16x2.f32 %0, %1, %2;" : "=r"(d) : "f"(c1), "f"(c0));
    return d;
}
__device__ __forceinline__ void packsplit2(float c0, float c1,
                                           uint32_t& hi, uint32_t& lo) {
    hi = pack_bf2(c0, c1);
    float h0 = __uint_as_float(hi << 16);
    float h1 = __uint_as_float(hi & 0xffff0000u);
    lo = pack_bf2(c0 - h0, c1 - h1);
}

// ---------------- fp32 -> bf16 hi/lo -----------------------------------------
__global__ void convert_split_kernel(const float* __restrict__ src,
                                     __nv_bfloat16* __restrict__ hi,
                                     __nv_bfloat16* __restrict__ lo, int n4) {
    int i = blockIdx.x * blockDim.x + threadIdx.x;
    if (i >= n4) return;
    float4 v = ((const float4*)src)[i];
    uint32_t h0, l0, h1, l1;
    packsplit2(v.x, v.y, h0, l0);
    packsplit2(v.z, v.w, h1, l1);
    ((uint32_t*)hi)[2 * i] = h0; ((uint32_t*)hi)[2 * i + 1] = h1;
    ((uint32_t*)lo)[2 * i] = l0; ((uint32_t*)lo)[2 * i + 1] = l1;
}

// ---------------- block mean -> bf16 hi/lo at row MTOK+blk -------------------
__global__ void block_mean_kernel(const float* __restrict__ x) {
    int blk = blockIdx.x;
    int c4  = threadIdx.x;
    const float4* xr = (const float4*)x + (size_t)blk * LBLK * (DIM / 4) + c4;
    float4 acc = make_float4(0.f, 0.f, 0.f, 0.f);
#pragma unroll 4
    for (int r = 0; r < LBLK; r++) {
        float4 v = xr[(size_t)r * (DIM / 4)];
        acc.x += v.x; acc.y += v.y; acc.z += v.z; acc.w += v.w;
    }
    const float s = 1.f / 64.f;
    acc.x *= s; acc.y *= s; acc.z *= s; acc.w *= s;
    uint32_t h0, l0, h1, l1;
    packsplit2(acc.x, acc.y, h0, l0);
    packsplit2(acc.z, acc.w, h1, l1);
    size_t base = ((size_t)(MTOK + blk) * DIM) / 2 + c4 * 2;
    ((uint32_t*)g_xh)[base] = h0; ((uint32_t*)g_xh)[base + 1] = h1;
    ((uint32_t*)g_xl)[base] = l0; ((uint32_t*)g_xl)[base + 1] = l1;
}

// ---------------- HMMA split-bf16 GEMM: 128x256 tile, 512 threads ------------
// mode 0: C fp32 (+bias). mode 1: write split bf16 pair Ch/Cl (+bias).
#define SROW 40
#define A_BYTES (128 * SROW * 2)            // 10240
#define B_BYTES (256 * SROW * 2)            // 20480
#define BUFSZ (2 * A_BYTES + 2 * B_BYTES)   // 61440
#define GEMM_SMEM (2 * BUFSZ)               // 122880

__global__ __launch_bounds__(512, 1) void gemm_hmma_split(
    const __nv_bfloat16* __restrict__ Ah, const __nv_bfloat16* __restrict__ Al,
    const __nv_bfloat16* __restrict__ Wh, const __nv_bfloat16* __restrict__ Wl,
    const float* __restrict__ bias, float* __restrict__ C,
    __nv_bfloat16* __restrict__ Ch, __nv_bfloat16* __restrict__ Cl,
    int Nout, int mode)
{
    extern __shared__ char smc[];
    const uint32_t sbase = smem_u32(smc);
    const int tid = threadIdx.x, wid = tid >> 5, lane = tid & 31;
    const int tN = blockIdx.x, tM = blockIdx.y;
    const int wm = wid & 3, wn = wid >> 2;          // 4m x 4n, warp 32x64

    const size_t arow0 = (size_t)tM * 128;
    const size_t wrow0 = (size_t)tN * 256;

    auto load_slab = [&](int s, int buf) {
        uint32_t sb = sbase + buf * BUFSZ;
        {
            int row = tid >> 2, q = tid & 3;
            cp_async16(sb + row * (SROW * 2) + q * 16,
                       Ah + (arow0 + row) * GK + s * 32 + q * 8);
            cp_async16(sb + A_BYTES + row * (SROW * 2) + q * 16,
                       Al + (arow0 + row) * GK + s * 32 + q * 8);
        }
#pragma unroll
        for (int i = 0; i < 2; i++) {
            int c = tid + 512 * i;
            int row = c >> 2, q = c & 3;
            cp_async16(sb + 2 * A_BYTES + row * (SROW * 2) + q * 16,
                       Wh + (wrow0 + row) * GK + s * 32 + q * 8);
            cp_async16(sb + 2 * A_BYTES + B_BYTES + row * (SROW * 2) + q * 16,
                       Wl + (wrow0 + row) * GK + s * 32 + q * 8);
        }
        CP_COMMIT();
    };

    float acc[2][8][4];
#pragma unroll
    for (int mi = 0; mi < 2; mi++)
#pragma unroll
        for (int ni = 0; ni < 8; ni++)
#pragma unroll
            for (int j = 0; j < 4; j++) acc[mi][ni][j] = 0.f;

    const int a_row = lane & 15, a_kq = lane >> 4;
    const int b_row = (lane & 7) + ((lane >> 4) << 3);
    const int b_kh = (lane >> 3) & 1;

    load_slab(0, 0);
    for (int s = 0; s < 16; s++) {
        if (s + 1 < 16) { load_slab(s + 1, (s + 1) & 1); CP_WAIT(1); }
        else            { CP_WAIT(0); }
        __syncthreads();

        const uint32_t sb = sbase + (s & 1) * BUFSZ;
#pragma unroll
        for (int kk = 0; kk < 2; kk++) {
            uint32_t af[2][2][4];
#pragma unroll
            for (int p = 0; p < 2; p++)
#pragma unroll
                for (int mi = 0; mi < 2; mi++) {
                    uint32_t addr = sb + p * A_BYTES +
                        (wm * 32 + mi * 16 + a_row) * (SROW * 2) +
                        (kk * 16 + a_kq * 8) * 2;
                    ldsm4(af[p][mi], addr);
                }
            uint32_t bf[2][8][2];
#pragma unroll
            for (int p = 0; p < 2; p++)
#pragma unroll
                for (int j = 0; j < 4; j++) {
                    uint32_t addr = sb + 2 * A_BYTES + p * B_BYTES +
                        (wn * 64 + j * 16 + b_row) * (SROW * 2) +
                        (kk * 16 + b_kh * 8) * 2;
                    uint32_t r[4];
                    ldsm4(r, addr);
                    bf[p][2 * j][0] = r[0]; bf[p][2 * j][1] = r[1];
                    bf[p][2 * j + 1][0] = r[2]; bf[p][2 * j + 1][1] = r[3];
                }
#pragma unroll
            for (int mi = 0; mi < 2; mi++)
#pragma unroll
                for (int ni = 0; ni < 8; ni++) {
                    mma16816(acc[mi][ni], af[0][mi], bf[0][ni][0], bf[0][ni][1]);
                    mma16816(acc[mi][ni], af[0][mi], bf[1][ni][0], bf[1][ni][1]);
                    mma16816(acc[mi][ni], af[1][mi], bf[0][ni][0], bf[0][ni][1]);
                }
        }
        __syncthreads();
    }

    const int r4 = lane >> 2, c2 = (lane & 3) * 2;
#pragma unroll
    for (int mi = 0; mi < 2; mi++) {
        int row = tM * 128 + wm * 32 + mi * 16 + r4;
#pragma unroll
        for (int ni = 0; ni < 8; ni++) {
            int col = tN * 256 + wn * 64 + ni * 8 + c2;
            float2 bv = *(const float2*)(bias + col);
            float o00 = acc[mi][ni][0] + bv.x, o01 = acc[mi][ni][1] + bv.y;
            float o10 = acc[mi][ni][2] + bv.x, o11 = acc[mi][ni][3] + bv.y;
            if (mode == 0) {
                *(float2*)(C + (size_t)row * Nout + col) = make_float2(o00, o01);
                *(float2*)(C + (size_t)(row + 8) * Nout + col) = make_float2(o10, o11);
            } else {
                uint32_t hi, lo;
                size_t idx0 = ((size_t)row * Nout + col) >> 1;
                packsplit2(o00, o01, hi, lo);
                ((uint32_t*)Ch)[idx0] = hi; ((uint32_t*)Cl)[idx0] = lo;
                size_t idx1 = ((size_t)(row + 8) * Nout + col) >> 1;
                packsplit2(o10, o11, hi, lo);
                ((uint32_t*)Ch)[idx1] = hi; ((uint32_t*)Cl)[idx1] = lo;
            }
        }
    }
}

// ---------------- HMMA attention per (head, block) ---------------------------
// smem (bf16, stride 72): qh[64], ql[64], kh[80], kl[80], vh[80], vl[80]
#define QH_OFF  0
#define QL_OFF  (64 * 72)        // 4608
#define KH_OFF  (QL_OFF + 64 * 72)
#define KL_OFF  (KH_OFF + 80 * 72)
#define VH_OFF  (KL_OFF + 80 * 72)
#define VL_OFF  (VH_OFF + 80 * 72)
#define ATTN_SMEM ((VL_OFF + 80 * 72) * 2)   // 64512 B

__global__ __launch_bounds__(128, 3) void attn_kernel(
    const float* __restrict__ edge, const int* __restrict__ mask,
    const float* __restrict__ eg_w, const float* __restrict__ eg_b)
{
    extern __shared__ __nv_bfloat16 sma[];
    const uint32_t sb32 = smem_u32(sma);
    const int h = blockIdx.x, blk = blockIdx.y;
    const int tid = threadIdx.x, wid = tid >> 5, lane = tid & 31;

    // zero pads: rows 65..79 of kh/kl/vh/vl (540 u32 each; offsets are even)
    for (int i = tid; i < 540; i += 128) {
        ((uint32_t*)&sma[KH_OFF + 65 * 72])[i] = 0u;
        ((uint32_t*)&sma[KL_OFF + 65 * 72])[i] = 0u;
        ((uint32_t*)&sma[VH_OFF + 65 * 72])[i] = 0u;
        ((uint32_t*)&sma[VL_OFF + 65 * 72])[i] = 0u;
    }

    // copy q (64x64) and k/v (65x64) split slices — pure uint2 memcpy
    for (int c = tid; c < 64 * 16; c += 128) {
        int r = c >> 4, p = c & 15;
        size_t g = (size_t)(blk * 64 + r) * QKVN + h * 64 + p * 4;
        *(uint2*)&sma[QH_OFF + r * 72 + p * 4] = *(const uint2*)&g_yh[g];
        *(uint2*)&sma[QL_OFF + r * 72 + p * 4] = *(const uint2*)&g_yl[g];
    }
    for (int c = tid; c < 65 * 16; c += 128) {
        int r = c >> 4, p = c & 15;
        size_t row = (r < 64) ? (size_t)(blk * 64 + r) : (size_t)(MTOK + blk);
        size_t gk = row * QKVN + DIM + h * 64 + p * 4;
        size_t gv = row * QKVN + 2 * DIM + h * 64 + p * 4;
        *(uint2*)&sma[KH_OFF + r * 72 + p * 4] = *(const uint2*)&g_yh[gk];
        *(uint2*)&sma[KL_OFF + r * 72 + p * 4] = *(const uint2*)&g_yl[gk];
        *(uint2*)&sma[VH_OFF + r * 72 + p * 4] = *(const uint2*)&g_yh[gv];
        *(uint2*)&sma[VL_OFF + r * 72 + p * 4] = *(const uint2*)&g_yl[gv];
    }
    __syncthreads();

    // ---- QK^T: warp owns q-rows q0..q0+15, key cols 0..71 (9 n8-tiles) ----
    const int q0 = wid * 16;
    const int a_row = lane & 15, a_k8 = (lane >> 4) * 8;
    const int b_row = (lane & 7) + ((lane >> 4) << 3);
    const int b_k8 = ((lane >> 3) & 1) * 8;

    float acc[9][4];
#pragma unroll
    for (int j = 0; j < 9; j++)
#pragma unroll
        for (int i = 0; i < 4; i++) acc[j][i] = 0.f;

#pragma unroll
    for (int kt = 0; kt < 4; kt++) {
        uint32_t ah4[4], al4[4];
        ldsm4(ah4, sb32 + (QH_OFF + (q0 + a_row) * 72 + kt * 16 + a_k8) * 2);
        ldsm4(al4, sb32 + (QL_OFF + (q0 + a_row) * 72 + kt * 16 + a_k8) * 2);
#pragma unroll
        for (int t5 = 0; t5 < 5; t5++) {
            uint32_t bh4[4], bl4[4];
            ldsm4(bh4, sb32 + (KH_OFF + (t5 * 16 + b_row) * 72 + kt * 16 + b_k8) * 2);
            ldsm4(bl4, sb32 + (KL_OFF + (t5 * 16 + b_row) * 72 + kt * 16 + b_k8) * 2);
            mma16816(acc[2 * t5], ah4, bh4[0], bh4[1]);
            mma16816(acc[2 * t5], ah4, bl4[0], bl4[1]);
            mma16816(acc[2 * t5], al4, bh4[0], bh4[1]);
            if (t5 < 4) {
                mma16816(acc[2 * t5 + 1], ah4, bh4[2], bh4[3]);
                mma16816(acc[2 * t5 + 1], ah4, bl4[2], bl4[3]);
                mma16816(acc[2 * t5 + 1], al4, bh4[2], bh4[3]);
            }
        }
    }

    // ---- softmax + bias + mask + lew (fp32), in fragment registers ----
    const int r4 = lane >> 2, c2b = (lane & 3) * 2;
    const float w0 = eg_w[h * 4 + 0], w1 = eg_w[h * 4 + 1];
    const float w2 = eg_w[h * 4 + 2], w3 = eg_w[h * 4 + 3];
    const float bhh = eg_b[h];
    const float lewd = w3 + bhh;
    const size_t ebase = (size_t)blk * 64 * KEYS;

    float lewf[9][2][2];
    float mx0 = -1e30f, mx1 = -1e30f;
#pragma unroll
    for (int j = 0; j < 9; j++) {
#pragma unroll
        for (int half = 0; half < 2; half++) {
            const int q = q0 + r4 + half * 8;
#pragma unroll
            for (int e = 0; e < 2; e++) {
                const int k = j * 8 + c2b + e;
                float s = acc[j][half * 2 + e];
                float sc, lw;
                if (k > 64) { sc = -1e30f; lw = 0.f; }
                else if (k == 64) { sc = s * 0.125f + 1.f; lw = lewd; }
                else {
                    int m = mask[ebase + (size_t)q * KEYS + k];
                    float4 ev = *(const float4*)(edge + (ebase + (size_t)q * KEYS + k) * 4);
                    float b;
                    if (k == q) { b = 1.f; lw = lewd; }
                    else { b = ev.w; lw = ev.x * w0 + ev.y * w1 + ev.z * w2 + ev.w * w3 + bhh; }
                    sc = s * 0.125f + b;
                    if (m == 0) { sc = -1e30f; lw = 0.f; }
                }
                acc[j][half * 2 + e] = sc;
                lewf[j][half][e] = lw;
                if (half == 0) mx0 = fmaxf(mx0, sc); else mx1 = fmaxf(mx1, sc);
            }
        }
    }
    mx0 = fmaxf(mx0, __shfl_xor_sync(0xffffffffu, mx0, 1));
    mx0 = fmaxf(mx0, __shfl_xor_sync(0xffffffffu, mx0, 2));
    mx1 = fmaxf(mx1, __shfl_xor_sync(0xffffffffu, mx1, 1));
    mx1 = fmaxf(mx1, __shfl_xor_sync(0xffffffffu, mx1, 2));

    float sum0 = 0.f, sum1 = 0.f;
#pragma unroll
    for (int j = 0; j < 9; j++) {
        float e0 = __expf(acc[j][0] - mx0); acc[j][0] = e0; sum0 += e0;
        float e1 = __expf(acc[j][1] - mx0); acc[j][1] = e1; sum0 += e1;
        float e2 = __expf(acc[j][2] - mx1); acc[j][2] = e2; sum1 += e2;
        float e3 = __expf(acc[j][3] - mx1); acc[j][3] = e3; sum1 += e3;
    }
    sum0 += __shfl_xor_sync(0xffffffffu, sum0, 1);
    sum0 += __shfl_xor_sync(0xffffffffu, sum0, 2);
    sum1 += __shfl_xor_sync(0xffffffffu, sum1, 1);
    sum1 += __shfl_xor_sync(0xffffffffu, sum1, 2);
    const float inv0 = 1.f / sum0, inv1 = 1.f / sum1;

    // combined -> split A fragments for PV
    uint32_t cah[5][4], cal[5][4];
#pragma unroll
    for (int kt = 0; kt < 5; kt++) {
#pragma unroll
        for (int jj = 0; jj < 2; jj++) {
            const int j = 2 * kt + jj;
#pragma unroll
            for (int half = 0; half < 2; half++) {
                if (j < 9) {
                    const float iv = half ? inv1 : inv0;
                    float c0 = acc[j][half * 2 + 0] * iv + lewf[j][half][0];
                    float c1 = acc[j][half * 2 + 1] * iv + lewf[j][half][1];
                    packsplit2(c0, c1, cah[kt][jj * 2 + half], cal[kt][jj * 2 + half]);
                } else {
                    cah[kt][jj * 2 + half] = 0u;
                    cal[kt][jj * 2 + half] = 0u;
                }
            }
        }
    }

    // ---- PV via trans-ldmatrix on row-major V ----
    float out[8][4];
#pragma unroll
    for (int n = 0; n < 8; n++)
#pragma unroll
        for (int i = 0; i < 4; i++) out[n][i] = 0.f;

#pragma unroll
    for (int kt = 0; kt < 5; kt++) {
#pragma unroll
        for (int g = 0; g < 4; g++) {
            uint32_t vh4[4], vl4[4];
            uint32_t adr = (kt * 16 + (lane & 15)) * 72 + g * 16 + ((lane >> 4) * 8);
            ldsm4t(vh4, sb32 + (VH_OFF + adr) * 2);
            ldsm4t(vl4, sb32 + (VL_OFF + adr) * 2);
            mma16816(out[2 * g],     cah[kt], vh4[0], vh4[1]);
            mma16816(out[2 * g],     cah[kt], vl4[0], vl4[1]);
            mma16816(out[2 * g],     cal[kt], vh4[0], vh4[1]);
            mma16816(out[2 * g + 1], cah[kt], vh4[2], vh4[3]);
            mma16816(out[2 * g + 1], cah[kt], vl4[2], vl4[3]);
            mma16816(out[2 * g + 1], cal[kt], vh4[2], vh4[3]);
        }
    }

    // ---- epilogue: write bf16 hi/lo pair ----
#pragma unroll
    for (int n = 0; n < 8; n++) {
        const int d = n * 8 + c2b;
#pragma unroll
        for (int half = 0; half < 2; half++) {
            const int q = q0 + r4 + half * 8;
            const size_t idx = ((size_t)(blk * 64 + q) * DIM + h * 64 + d) >> 1;
            uint32_t hi, lo;
            packsplit2(out[n][half * 2], out[n][half * 2 + 1], hi, lo);
            ((uint32_t*)g_aoh)[idx] = hi;
            ((uint32_t*)g_aol)[idx] = lo;
        }
    }
}

// ---------------- host -------------------------------------------------------
extern "C" void kernel_launch(void* const* d_in, const int* in_sizes, int n_in,
                              void* d_out, int out_size)
{
    const float* x      = (const float*)d_in[0];
    const int*   mask   = (const int*)  d_in[1];
    const float* edge   = (const float*)d_in[2];
    const float* qkv_w  = (const float*)d_in[3];
    const float* qkv_b  = (const float*)d_in[4];
    const float* proj_w = (const float*)d_in[5];
    const float* proj_b = (const float*)d_in[6];
    const float* eg_w   = (const float*)d_in[7];
    const float* eg_b   = (const float*)d_in[8];
    float* out = (float*)d_out;

    void *p_xh, *p_xl, *p_yh, *p_yl, *p_aoh, *p_aol, *p_qwh, *p_qwl, *p_pwh, *p_pwl;
    cudaGetSymbolAddress(&p_xh, g_xh);   cudaGetSymbolAddress(&p_xl, g_xl);
    cudaGetSymbolAddress(&p_yh, g_yh);   cudaGetSymbolAddress(&p_yl, g_yl);
    cudaGetSymbolAddress(&p_aoh, g_aoh); cudaGetSymbolAddress(&p_aol, g_aol);
    cudaGetSymbolAddress(&p_qwh, g_qwh); cudaGetSymbolAddress(&p_qwl, g_qwl);
    cudaGetSymbolAddress(&p_pwh, g_pwh); cudaGetSymbolAddress(&p_pwl, g_pwl);

    cudaFuncSetAttribute(gemm_hmma_split, cudaFuncAttributeMaxDynamicSharedMemorySize, GEMM_SMEM);
    cudaFuncSetAttribute(attn_kernel, cudaFuncAttributeMaxDynamicSharedMemorySize, ATTN_SMEM);

    convert_split_kernel<<<(MTOK * DIM / 4 + 255) / 256, 256>>>(
        x, (__nv_bfloat16*)p_xh, (__nv_bfloat16*)p_xl, MTOK * DIM / 4);
    convert_split_kernel<<<(QKVN * DIM / 4 + 255) / 256, 256>>>(
        qkv_w, (__nv_bfloat16*)p_qwh, (__nv_bfloat16*)p_qwl, QKVN * DIM / 4);
    convert_split_kernel<<<(DIM * DIM / 4 + 255) / 256, 256>>>(
        proj_w, (__nv_bfloat16*)p_pwh, (__nv_bfloat16*)p_pwl, DIM * DIM / 4);
    block_mean_kernel<<<NBLK, 128>>>(x);

    dim3 g1(QKVN / 256, MAUG / 128);          // (6, 520)
    gemm_hmma_split<<<g1, 512, GEMM_SMEM>>>(
        (const __nv_bfloat16*)p_xh, (const __nv_bfloat16*)p_xl,
        (const __nv_bfloat16*)p_qwh, (const __nv_bfloat16*)p_qwl,
        qkv_b, nullptr,
        (__nv_bfloat16*)p_yh, (__nv_bfloat16*)p_yl, QKVN, 1);

    dim3 g2(NHEAD, NBLK);                     // (8, 1024): heads adjacent
    attn_kernel<<<g2, 128, ATTN_SMEM>>>(edge, mask, eg_w, eg_b);

    dim3 g3(DIM / 256, MTOK / 128);           // (2, 512)
    gemm_hmma_split<<<g3, 512, GEMM_SMEM>>>(
        (const __nv_bfloat16*)p_aoh, (const __nv_bfloat16*)p_aol,
        (const __nv_bfloat16*)p_pwh, (const __nv_bfloat16*)p_pwl,
        proj_b, out, nullptr, nullptr, DIM, 0);
}

// round 7
// speedup vs baseline: 1.2086x; 1.2086x over previous
#include <cuda_runtime.h>
#include <cuda_fp16.h>
#include <cstdint>
#include <math.h>

#define DIM   512
#define LBLK  64
#define NHEAD 8
#define KEYS  65
#define BB    2
#define NTOK  32768
#define NBPB  512
#define NBLK  (BB*NBPB)           // 1024
#define MTOK  (BB*NTOK)           // 65536
#define MAUG  (MTOK+NBLK)         // 66560
#define QKVN  (3*DIM)             // 1536
#define GK    512

// ---------------- scratch ----------------------------------------------------
__device__ __half g_xh[(size_t)MAUG * DIM];
__device__ __half g_xl[(size_t)MAUG * DIM];
__device__ __half g_yh[(size_t)MAUG * QKVN];   // split qkv hi
__device__ __half g_yl[(size_t)MAUG * QKVN];   // split qkv lo
__device__ __half g_aoh[(size_t)MTOK * DIM];
__device__ __half g_aol[(size_t)MTOK * DIM];
__device__ __half g_qw[(size_t)QKVN * DIM];    // qkv weights, single fp16
__device__ __half g_pwh[(size_t)DIM * DIM];    // proj weights hi
__device__ __half g_pwl[(size_t)DIM * DIM];    // proj weights lo

// ---------------- helpers ----------------------------------------------------
__device__ __forceinline__ uint32_t smem_u32(const void* p) {
    uint32_t a;
    asm("{ .reg .u64 t; cvta.to.shared.u64 t, %1; cvt.u32.u64 %0, t; }"
        : "=r"(a) : "l"(p));
    return a;
}
__device__ __forceinline__ void cp_async16(uint32_t dst, const void* src) {
    asm volatile("cp.async.cg.shared.global [%0], [%1], 16;"
                 :: "r"(dst), "l"(src) : "memory");
}
#define CP_COMMIT() asm volatile("cp.async.commit_group;" ::: "memory")
#define CP_WAIT(n)  asm volatile("cp.async.wait_group %0;" :: "n"(n) : "memory")

__device__ __forceinline__ void ldsm4(uint32_t (&r)[4], uint32_t addr) {
    asm volatile("ldmatrix.sync.aligned.m8n8.x4.shared.b16 {%0,%1,%2,%3}, [%4];"
                 : "=r"(r[0]), "=r"(r[1]), "=r"(r[2]), "=r"(r[3]) : "r"(addr));
}
__device__ __forceinline__ void ldsm4t(uint32_t (&r)[4], uint32_t addr) {
    asm volatile("ldmatrix.sync.aligned.m8n8.x4.trans.shared.b16 {%0,%1,%2,%3}, [%4];"
                 : "=r"(r[0]), "=r"(r[1]), "=r"(r[2]), "=r"(r[3]) : "r"(addr));
}
__device__ __forceinline__ void mma16816h(float (&d)[4], const uint32_t (&a)[4],
                                          const uint32_t b0, const uint32_t b1) {
    asm volatile(
        "mma.sync.aligned.m16n8k16.row.col.f32.f16.f16.f32 "
        "{%0,%1,%2,%3}, {%4,%5,%6,%7}, {%8,%9}, {%0,%1,%2,%3};"
        : "+f"(d[0]), "+f"(d[1]), "+f"(d[2]), "+f"(d[3])
        : "r"(a[0]), "r"(a[1]), "r"(a[2]), "r"(a[3]), "r"(b0), "r"(b1));
}
__device__ __forceinline__ void packsplit2h(float c0, float c1,
                                            uint32_t& hi, uint32_t& lo) {
    __half2 h = __floats2half2_rn(c0, c1);
    float2 hf = __half22float2(h);
    __half2 l = __floats2half2_rn(c0 - hf.x, c1 - hf.y);
    hi = *reinterpret_cast<uint32_t*>(&h);
    lo = *reinterpret_cast<uint32_t*>(&l);
}

// ---------------- weight converts -------------------------------------------
__global__ void convert_half_kernel(const float* __restrict__ src,
                                    __half* __restrict__ dst, int n4) {
    int i = blockIdx.x * blockDim.x + threadIdx.x;
    if (i >= n4) return;
    float4 v = ((const float4*)src)[i];
    __half2 a = __floats2half2_rn(v.x, v.y);
    __half2 b = __floats2half2_rn(v.z, v.w);
    ((__half2*)dst)[2 * i] = a;
    ((__half2*)dst)[2 * i + 1] = b;
}
__global__ void convert_split_h_kernel(const float* __restrict__ src,
                                       __half* __restrict__ hi,
                                       __half* __restrict__ lo, int n4) {
    int i = blockIdx.x * blockDim.x + threadIdx.x;
    if (i >= n4) return;
    float4 v = ((const float4*)src)[i];
    uint32_t h0, l0, h1, l1;
    packsplit2h(v.x, v.y, h0, l0);
    packsplit2h(v.z, v.w, h1, l1);
    ((uint32_t*)hi)[2 * i] = h0; ((uint32_t*)hi)[2 * i + 1] = h1;
    ((uint32_t*)lo)[2 * i] = l0; ((uint32_t*)lo)[2 * i + 1] = l1;
}

// ---------------- fused x split-convert + block mean -------------------------
__global__ void x_convert_mean_kernel(const float* __restrict__ x) {
    int blk = blockIdx.x;
    int c4  = threadIdx.x;          // 0..127
    const float4* xr = (const float4*)x + (size_t)blk * LBLK * (DIM / 4) + c4;
    float4 acc = make_float4(0.f, 0.f, 0.f, 0.f);
    for (int r = 0; r < LBLK; r++) {
        float4 v = xr[(size_t)r * (DIM / 4)];
        uint32_t h0, l0, h1, l1;
        packsplit2h(v.x, v.y, h0, l0);
        packsplit2h(v.z, v.w, h1, l1);
        size_t base = ((size_t)(blk * LBLK + r) * DIM) / 2 + c4 * 2;
        ((uint32_t*)g_xh)[base] = h0; ((uint32_t*)g_xh)[base + 1] = h1;
        ((uint32_t*)g_xl)[base] = l0; ((uint32_t*)g_xl)[base + 1] = l1;
        acc.x += v.x; acc.y += v.y; acc.z += v.z; acc.w += v.w;
    }
    const float s = 1.f / 64.f;
    acc.x *= s; acc.y *= s; acc.z *= s; acc.w *= s;
    uint32_t h0, l0, h1, l1;
    packsplit2h(acc.x, acc.y, h0, l0);
    packsplit2h(acc.z, acc.w, h1, l1);
    size_t base = ((size_t)(MTOK + blk) * DIM) / 2 + c4 * 2;
    ((uint32_t*)g_xh)[base] = h0; ((uint32_t*)g_xh)[base + 1] = h1;
    ((uint32_t*)g_xl)[base] = l0; ((uint32_t*)g_xl)[base + 1] = l1;
}

// ---------------- HMMA GEMM: 128x256 tile, 512 threads -----------------------
// NPROD==2: A split (Ah,Al), W single (Wh).  acc = AhW + AlW
// NPROD==3: A split, W split.                acc = AhWh + AhWl + AlWh
// MODE==0: C fp32 + bias.  MODE==1: split fp16 (Ch, Cl) + bias.
#define SROW 40
#define A_BYTES (128 * SROW * 2)            // 10240
#define B_BYTES (256 * SROW * 2)            // 20480

template<int NPROD, int MODE>
__global__ __launch_bounds__(512, 1) void gemm_hmma(
    const __half* __restrict__ Ah, const __half* __restrict__ Al,
    const __half* __restrict__ Wh, const __half* __restrict__ Wl,
    const float* __restrict__ bias, float* __restrict__ C,
    __half* __restrict__ Ch, __half* __restrict__ Cl, int Nout)
{
    constexpr int WB = (NPROD == 3) ? 2 * B_BYTES : B_BYTES;
    constexpr int BUFSZ = 2 * A_BYTES + WB;

    extern __shared__ char smc[];
    const uint32_t sbase = smem_u32(smc);
    const int tid = threadIdx.x, wid = tid >> 5, lane = tid & 31;
    const int tN = blockIdx.x, tM = blockIdx.y;
    const int wm = wid & 3, wn = wid >> 2;          // 4m x 4n, warp 32x64

    const size_t arow0 = (size_t)tM * 128;
    const size_t wrow0 = (size_t)tN * 256;

    auto load_slab = [&](int s, int buf) {
        uint32_t sb = sbase + buf * BUFSZ;
        {
            int row = tid >> 2, q = tid & 3;
            cp_async16(sb + row * (SROW * 2) + q * 16,
                       Ah + (arow0 + row) * GK + s * 32 + q * 8);
            cp_async16(sb + A_BYTES + row * (SROW * 2) + q * 16,
                       Al + (arow0 + row) * GK + s * 32 + q * 8);
        }
#pragma unroll
        for (int i = 0; i < 2; i++) {
            int c = tid + 512 * i;
            int row = c >> 2, q = c & 3;
            cp_async16(sb + 2 * A_BYTES + row * (SROW * 2) + q * 16,
                       Wh + (wrow0 + row) * GK + s * 32 + q * 8);
            if (NPROD == 3)
                cp_async16(sb + 2 * A_BYTES + B_BYTES + row * (SROW * 2) + q * 16,
                           Wl + (wrow0 + row) * GK + s * 32 + q * 8);
        }
        CP_COMMIT();
    };

    float acc[2][8][4];
#pragma unroll
    for (int mi = 0; mi < 2; mi++)
#pragma unroll
        for (int ni = 0; ni < 8; ni++)
#pragma unroll
            for (int j = 0; j < 4; j++) acc[mi][ni][j] = 0.f;

    const int a_row = lane & 15, a_kq = lane >> 4;
    const int b_row = (lane & 7) + ((lane >> 4) << 3);
    const int b_kh = (lane >> 3) & 1;

    load_slab(0, 0);
    for (int s = 0; s < 16; s++) {
        if (s + 1 < 16) { load_slab(s + 1, (s + 1) & 1); CP_WAIT(1); }
        else            { CP_WAIT(0); }
        __syncthreads();

        const uint32_t sb = sbase + (s & 1) * BUFSZ;
#pragma unroll
        for (int kk = 0; kk < 2; kk++) {
            uint32_t af[2][2][4];
#pragma unroll
            for (int p = 0; p < 2; p++)
#pragma unroll
                for (int mi = 0; mi < 2; mi++) {
                    uint32_t addr = sb + p * A_BYTES +
                        (wm * 32 + mi * 16 + a_row) * (SROW * 2) +
                        (kk * 16 + a_kq * 8) * 2;
                    ldsm4(af[p][mi], addr);
                }
            uint32_t bf[2][8][2];
#pragma unroll
            for (int p = 0; p < NPROD - 1; p++)
#pragma unroll
                for (int j = 0; j < 4; j++) {
                    uint32_t addr = sb + 2 * A_BYTES + p * B_BYTES +
                        (wn * 64 + j * 16 + b_row) * (SROW * 2) +
                        (kk * 16 + b_kh * 8) * 2;
                    uint32_t r[4];
                    ldsm4(r, addr);
                    bf[p][2 * j][0] = r[0]; bf[p][2 * j][1] = r[1];
                    bf[p][2 * j + 1][0] = r[2]; bf[p][2 * j + 1][1] = r[3];
                }
#pragma unroll
            for (int mi = 0; mi < 2; mi++)
#pragma unroll
                for (int ni = 0; ni < 8; ni++) {
                    mma16816h(acc[mi][ni], af[0][mi], bf[0][ni][0], bf[0][ni][1]);
                    if (NPROD == 3)
                        mma16816h(acc[mi][ni], af[0][mi], bf[1][ni][0], bf[1][ni][1]);
                    mma16816h(acc[mi][ni], af[1][mi], bf[0][ni][0], bf[0][ni][1]);
                }
        }
        __syncthreads();
    }

    const int r4 = lane >> 2, c2 = (lane & 3) * 2;
#pragma unroll
    for (int mi = 0; mi < 2; mi++) {
        int row = tM * 128 + wm * 32 + mi * 16 + r4;
#pragma unroll
        for (int ni = 0; ni < 8; ni++) {
            int col = tN * 256 + wn * 64 + ni * 8 + c2;
            float2 bv = *(const float2*)(bias + col);
            float o00 = acc[mi][ni][0] + bv.x, o01 = acc[mi][ni][1] + bv.y;
            float o10 = acc[mi][ni][2] + bv.x, o11 = acc[mi][ni][3] + bv.y;
            if (MODE == 0) {
                *(float2*)(C + (size_t)row * Nout + col) = make_float2(o00, o01);
                *(float2*)(C + (size_t)(row + 8) * Nout + col) = make_float2(o10, o11);
            } else {
                uint32_t hi, lo;
                size_t idx0 = ((size_t)row * Nout + col) >> 1;
                packsplit2h(o00, o01, hi, lo);
                ((uint32_t*)Ch)[idx0] = hi; ((uint32_t*)Cl)[idx0] = lo;
                size_t idx1 = ((size_t)(row + 8) * Nout + col) >> 1;
                packsplit2h(o10, o11, hi, lo);
                ((uint32_t*)Ch)[idx1] = hi; ((uint32_t*)Cl)[idx1] = lo;
            }
        }
    }
}

// ---------------- HMMA attention per (head, block) ---------------------------
// smem (half, stride 72): qh[64], ql[64], kh[80], kl[80], vh[80], vl[80]
#define QH_OFF  0
#define QL_OFF  (64 * 72)
#define KH_OFF  (QL_OFF + 64 * 72)
#define KL_OFF  (KH_OFF + 80 * 72)
#define VH_OFF  (KL_OFF + 80 * 72)
#define VL_OFF  (VH_OFF + 80 * 72)
#define ATTN_SMEM ((VL_OFF + 80 * 72) * 2)   // 64512 B

__global__ __launch_bounds__(128, 3) void attn_kernel(
    const float* __restrict__ edge, const int* __restrict__ mask,
    const float* __restrict__ eg_w, const float* __restrict__ eg_b)
{
    extern __shared__ __half sma[];
    const uint32_t sb32 = smem_u32(sma);
    const int h = blockIdx.x, blk = blockIdx.y;
    const int tid = threadIdx.x, wid = tid >> 5, lane = tid & 31;

    for (int i = tid; i < 540; i += 128) {
        ((uint32_t*)&sma[KH_OFF + 65 * 72])[i] = 0u;
        ((uint32_t*)&sma[KL_OFF + 65 * 72])[i] = 0u;
        ((uint32_t*)&sma[VH_OFF + 65 * 72])[i] = 0u;
        ((uint32_t*)&sma[VL_OFF + 65 * 72])[i] = 0u;
    }

    for (int c = tid; c < 64 * 16; c += 128) {
        int r = c >> 4, p = c & 15;
        size_t g = (size_t)(blk * 64 + r) * QKVN + h * 64 + p * 4;
        *(uint2*)&sma[QH_OFF + r * 72 + p * 4] = *(const uint2*)&g_yh[g];
        *(uint2*)&sma[QL_OFF + r * 72 + p * 4] = *(const uint2*)&g_yl[g];
    }
    for (int c = tid; c < 65 * 16; c += 128) {
        int r = c >> 4, p = c & 15;
        size_t row = (r < 64) ? (size_t)(blk * 64 + r) : (size_t)(MTOK + blk);
        size_t gk = row * QKVN + DIM + h * 64 + p * 4;
        size_t gv = row * QKVN + 2 * DIM + h * 64 + p * 4;
        *(uint2*)&sma[KH_OFF + r * 72 + p * 4] = *(const uint2*)&g_yh[gk];
        *(uint2*)&sma[KL_OFF + r * 72 + p * 4] = *(const uint2*)&g_yl[gk];
        *(uint2*)&sma[VH_OFF + r * 72 + p * 4] = *(const uint2*)&g_yh[gv];
        *(uint2*)&sma[VL_OFF + r * 72 + p * 4] = *(const uint2*)&g_yl[gv];
    }
    __syncthreads();

    const int q0 = wid * 16;
    const int a_row = lane & 15, a_k8 = (lane >> 4) * 8;
    const int b_row = (lane & 7) + ((lane >> 4) << 3);
    const int b_k8 = ((lane >> 3) & 1) * 8;

    float acc[9][4];
#pragma unroll
    for (int j = 0; j < 9; j++)
#pragma unroll
        for (int i = 0; i < 4; i++) acc[j][i] = 0.f;

#pragma unroll
    for (int kt = 0; kt < 4; kt++) {
        uint32_t ah4[4], al4[4];
        ldsm4(ah4, sb32 + (QH_OFF + (q0 + a_row) * 72 + kt * 16 + a_k8) * 2);
        ldsm4(al4, sb32 + (QL_OFF + (q0 + a_row) * 72 + kt * 16 + a_k8) * 2);
#pragma unroll
        for (int t5 = 0; t5 < 5; t5++) {
            uint32_t bh4[4], bl4[4];
            ldsm4(bh4, sb32 + (KH_OFF + (t5 * 16 + b_row) * 72 + kt * 16 + b_k8) * 2);
            ldsm4(bl4, sb32 + (KL_OFF + (t5 * 16 + b_row) * 72 + kt * 16 + b_k8) * 2);
            mma16816h(acc[2 * t5], ah4, bh4[0], bh4[1]);
            mma16816h(acc[2 * t5], ah4, bl4[0], bl4[1]);
            mma16816h(acc[2 * t5], al4, bh4[0], bh4[1]);
            if (t5 < 4) {
                mma16816h(acc[2 * t5 + 1], ah4, bh4[2], bh4[3]);
                mma16816h(acc[2 * t5 + 1], ah4, bl4[2], bl4[3]);
                mma16816h(acc[2 * t5 + 1], al4, bh4[2], bh4[3]);
            }
        }
    }

    const int r4 = lane >> 2, c2b = (lane & 3) * 2;
    const float w0 = eg_w[h * 4 + 0], w1 = eg_w[h * 4 + 1];
    const float w2 = eg_w[h * 4 + 2], w3 = eg_w[h * 4 + 3];
    const float bhh = eg_b[h];
    const float lewd = w3 + bhh;
    const size_t ebase = (size_t)blk * 64 * KEYS;

    float lewf[9][2][2];
    float mx0 = -1e30f, mx1 = -1e30f;
#pragma unroll
    for (int j = 0; j < 9; j++) {
#pragma unroll
        for (int half = 0; half < 2; half++) {
            const int q = q0 + r4 + half * 8;
#pragma unroll
            for (int e = 0; e < 2; e++) {
                const int k = j * 8 + c2b + e;
                float s = acc[j][half * 2 + e];
                float sc, lw;
                if (k > 64) { sc = -1e30f; lw = 0.f; }
                else if (k == 64) { sc = s * 0.125f + 1.f; lw = lewd; }
                else {
                    int m = mask[ebase + (size_t)q * KEYS + k];
                    float4 ev = *(const float4*)(edge + (ebase + (size_t)q * KEYS + k) * 4);
                    float b;
                    if (k == q) { b = 1.f; lw = lewd; }
                    else { b = ev.w; lw = ev.x * w0 + ev.y * w1 + ev.z * w2 + ev.w * w3 + bhh; }
                    sc = s * 0.125f + b;
                    if (m == 0) { sc = -1e30f; lw = 0.f; }
                }
                acc[j][half * 2 + e] = sc;
                lewf[j][half][e] = lw;
                if (half == 0) mx0 = fmaxf(mx0, sc); else mx1 = fmaxf(mx1, sc);
            }
        }
    }
    mx0 = fmaxf(mx0, __shfl_xor_sync(0xffffffffu, mx0, 1));
    mx0 = fmaxf(mx0, __shfl_xor_sync(0xffffffffu, mx0, 2));
    mx1 = fmaxf(mx1, __shfl_xor_sync(0xffffffffu, mx1, 1));
    mx1 = fmaxf(mx1, __shfl_xor_sync(0xffffffffu, mx1, 2));

    float sum0 = 0.f, sum1 = 0.f;
#pragma unroll
    for (int j = 0; j < 9; j++) {
        float e0 = __expf(acc[j][0] - mx0); acc[j][0] = e0; sum0 += e0;
        float e1 = __expf(acc[j][1] - mx0); acc[j][1] = e1; sum0 += e1;
        float e2 = __expf(acc[j][2] - mx1); acc[j][2] = e2; sum1 += e2;
        float e3 = __expf(acc[j][3] - mx1); acc[j][3] = e3; sum1 += e3;
    }
    sum0 += __shfl_xor_sync(0xffffffffu, sum0, 1);
    sum0 += __shfl_xor_sync(0xffffffffu, sum0, 2);
    sum1 += __shfl_xor_sync(0xffffffffu, sum1, 1);
    sum1 += __shfl_xor_sync(0xffffffffu, sum1, 2);
    const float inv0 = 1.f / sum0, inv1 = 1.f / sum1;

    uint32_t cah[5][4], cal[5][4];
#pragma unroll
    for (int kt = 0; kt < 5; kt++) {
#pragma unroll
        for (int jj = 0; jj < 2; jj++) {
            const int j = 2 * kt + jj;
#pragma unroll
            for (int half = 0; half < 2; half++) {
                if (j < 9) {
                    const float iv = half ? inv1 : inv0;
                    float c0 = acc[j][half * 2 + 0] * iv + lewf[j][half][0];
                    float c1 = acc[j][half * 2 + 1] * iv + lewf[j][half][1];
                    packsplit2h(c0, c1, cah[kt][jj * 2 + half], cal[kt][jj * 2 + half]);
                } else {
                    cah[kt][jj * 2 + half] = 0u;
                    cal[kt][jj * 2 + half] = 0u;
                }
            }
        }
    }

    float out[8][4];
#pragma unroll
    for (int n = 0; n < 8; n++)
#pragma unroll
        for (int i = 0; i < 4; i++) out[n][i] = 0.f;

#pragma unroll
    for (int kt = 0; kt < 5; kt++) {
#pragma unroll
        for (int g = 0; g < 4; g++) {
            uint32_t vh4[4], vl4[4];
            uint32_t adr = (kt * 16 + (lane & 15)) * 72 + g * 16 + ((lane >> 4) * 8);
            ldsm4t(vh4, sb32 + (VH_OFF + adr) * 2);
            ldsm4t(vl4, sb32 + (VL_OFF + adr) * 2);
            mma16816h(out[2 * g],     cah[kt], vh4[0], vh4[1]);
            mma16816h(out[2 * g],     cah[kt], vl4[0], vl4[1]);
            mma16816h(out[2 * g],     cal[kt], vh4[0], vh4[1]);
            mma16816h(out[2 * g + 1], cah[kt], vh4[2], vh4[3]);
            mma16816h(out[2 * g + 1], cah[kt], vl4[2], vl4[3]);
            mma16816h(out[2 * g + 1], cal[kt], vh4[2], vh4[3]);
        }
    }

#pragma unroll
    for (int n = 0; n < 8; n++) {
        const int d = n * 8 + c2b;
#pragma unroll
        for (int half = 0; half < 2; half++) {
            const int q = q0 + r4 + half * 8;
            const size_t idx = ((size_t)(blk * 64 + q) * DIM + h * 64 + d) >> 1;
            uint32_t hi, lo;
            packsplit2h(out[n][half * 2], out[n][half * 2 + 1], hi, lo);
            ((uint32_t*)g_aoh)[idx] = hi;
            ((uint32_t*)g_aol)[idx] = lo;
        }
    }
}

// ---------------- host -------------------------------------------------------
extern "C" void kernel_launch(void* const* d_in, const int* in_sizes, int n_in,
                              void* d_out, int out_size)
{
    const float* x      = (const float*)d_in[0];
    const int*   mask   = (const int*)  d_in[1];
    const float* edge   = (const float*)d_in[2];
    const float* qkv_w  = (const float*)d_in[3];
    const float* qkv_b  = (const float*)d_in[4];
    const float* proj_w = (const float*)d_in[5];
    const float* proj_b = (const float*)d_in[6];
    const float* eg_w   = (const float*)d_in[7];
    const float* eg_b   = (const float*)d_in[8];
    float* out = (float*)d_out;

    void *p_xh, *p_xl, *p_yh, *p_yl, *p_aoh, *p_aol, *p_qw, *p_pwh, *p_pwl;
    cudaGetSymbolAddress(&p_xh, g_xh);   cudaGetSymbolAddress(&p_xl, g_xl);
    cudaGetSymbolAddress(&p_yh, g_yh);   cudaGetSymbolAddress(&p_yl, g_yl);
    cudaGetSymbolAddress(&p_aoh, g_aoh); cudaGetSymbolAddress(&p_aol, g_aol);
    cudaGetSymbolAddress(&p_qw, g_qw);
    cudaGetSymbolAddress(&p_pwh, g_pwh); cudaGetSymbolAddress(&p_pwl, g_pwl);

    const int qkv_smem  = 2 * (2 * A_BYTES + B_BYTES);       // 81920
    const int proj_smem = 2 * (2 * A_BYTES + 2 * B_BYTES);   // 122880
    cudaFuncSetAttribute(gemm_hmma<2, 1>, cudaFuncAttributeMaxDynamicSharedMemorySize, qkv_smem);
    cudaFuncSetAttribute(gemm_hmma<3, 0>, cudaFuncAttributeMaxDynamicSharedMemorySize, proj_smem);
    cudaFuncSetAttribute(attn_kernel, cudaFuncAttributeMaxDynamicSharedMemorySize, ATTN_SMEM);

    // 1. conversions (x fused with block mean; weights)
    x_convert_mean_kernel<<<NBLK, 128>>>(x);
    convert_half_kernel<<<(QKVN * DIM / 4 + 255) / 256, 256>>>(
        qkv_w, (__half*)p_qw, QKVN * DIM / 4);
    convert_split_h_kernel<<<(DIM * DIM / 4 + 255) / 256, 256>>>(
        proj_w, (__half*)p_pwh, (__half*)p_pwl, DIM * DIM / 4);

    // 2. QKV GEMM: 2-product, split fp16 output
    dim3 g1(QKVN / 256, MAUG / 128);          // (6, 520)
    gemm_hmma<2, 1><<<g1, 512, qkv_smem>>>(
        (const __half*)p_xh, (const __half*)p_xl,
        (const __half*)p_qw, nullptr,
        qkv_b, nullptr, (__half*)p_yh, (__half*)p_yl, QKVN);

    // 3. attention
    dim3 g2(NHEAD, NBLK);
    attn_kernel<<<g2, 128, ATTN_SMEM>>>(edge, mask, eg_w, eg_b);

    // 4. proj GEMM: 3-product, fp32 output
    dim3 g3(DIM / 256, MTOK / 128);           // (2, 512)
    gemm_hmma<3, 0><<<g3, 512, proj_smem>>>(
        (const __half*)p_aoh, (const __half*)p_aol,
        (const __half*)p_pwh, (const __half*)p_pwl,
        proj_b, out, nullptr, nullptr, DIM);
}

// round 9
// speedup vs baseline: 1.3509x; 1.1178x over previous
#include <cuda_runtime.h>
#include <cuda_fp16.h>
#include <cstdint>
#include <math.h>

#define DIM   512
#define LBLK  64
#define NHEAD 8
#define KEYS  65
#define BB    2
#define NTOK  32768
#define NBPB  512
#define NBLK  (BB*NBPB)           // 1024
#define MTOK  (BB*NTOK)           // 65536
#define MAUG  (MTOK+NBLK)         // 66560
#define QKVN  (3*DIM)             // 1536
#define GK    512

// ---------------- scratch ----------------------------------------------------
__device__ __half g_xh[(size_t)MAUG * DIM];
__device__ __half g_xl[(size_t)MAUG * DIM];
__device__ __half g_yh[(size_t)MAUG * QKVN];
__device__ __half g_yl[(size_t)MAUG * QKVN];
__device__ __half g_aoh[(size_t)MTOK * DIM];
__device__ __half g_aol[(size_t)MTOK * DIM];
__device__ __half g_qw[(size_t)QKVN * DIM];
__device__ __half g_pwh[(size_t)DIM * DIM];
__device__ __half g_pwl[(size_t)DIM * DIM];

// ---------------- helpers ----------------------------------------------------
__device__ __forceinline__ uint32_t smem_u32(const void* p) {
    uint32_t a;
    asm("{ .reg .u64 t; cvta.to.shared.u64 t, %1; cvt.u32.u64 %0, t; }"
        : "=r"(a) : "l"(p));
    return a;
}
__device__ __forceinline__ void cp_async16(uint32_t dst, const void* src) {
    asm volatile("cp.async.cg.shared.global [%0], [%1], 16;"
                 :: "r"(dst), "l"(src) : "memory");
}
#define CP_COMMIT() asm volatile("cp.async.commit_group;" ::: "memory")
#define CP_WAIT(n)  asm volatile("cp.async.wait_group %0;" :: "n"(n) : "memory")

__device__ __forceinline__ void ldsm4(uint32_t (&r)[4], uint32_t addr) {
    asm volatile("ldmatrix.sync.aligned.m8n8.x4.shared.b16 {%0,%1,%2,%3}, [%4];"
                 : "=r"(r[0]), "=r"(r[1]), "=r"(r[2]), "=r"(r[3]) : "r"(addr));
}
__device__ __forceinline__ void ldsm4t(uint32_t (&r)[4], uint32_t addr) {
    asm volatile("ldmatrix.sync.aligned.m8n8.x4.trans.shared.b16 {%0,%1,%2,%3}, [%4];"
                 : "=r"(r[0]), "=r"(r[1]), "=r"(r[2]), "=r"(r[3]) : "r"(addr));
}
__device__ __forceinline__ void mma16816h(float (&d)[4], const uint32_t (&a)[4],
                                          const uint32_t b0, const uint32_t b1) {
    asm volatile(
        "mma.sync.aligned.m16n8k16.row.col.f32.f16.f16.f32 "
        "{%0,%1,%2,%3}, {%4,%5,%6,%7}, {%8,%9}, {%0,%1,%2,%3};"
        : "+f"(d[0]), "+f"(d[1]), "+f"(d[2]), "+f"(d[3])
        : "r"(a[0]), "r"(a[1]), "r"(a[2]), "r"(a[3]), "r"(b0), "r"(b1));
}
__device__ __forceinline__ void packsplit2h(float c0, float c1,
                                            uint32_t& hi, uint32_t& lo) {
    __half2 h = __floats2half2_rn(c0, c1);
    float2 hf = __half22float2(h);
    __half2 l = __floats2half2_rn(c0 - hf.x, c1 - hf.y);
    hi = *reinterpret_cast<uint32_t*>(&h);
    lo = *reinterpret_cast<uint32_t*>(&l);
}

// ---------------- weight converts -------------------------------------------
__global__ void convert_half_kernel(const float* __restrict__ src,
                                    __half* __restrict__ dst, int n4) {
    int i = blockIdx.x * blockDim.x + threadIdx.x;
    if (i >= n4) return;
    float4 v = ((const float4*)src)[i];
    ((__half2*)dst)[2 * i]     = __floats2half2_rn(v.x, v.y);
    ((__half2*)dst)[2 * i + 1] = __floats2half2_rn(v.z, v.w);
}
__global__ void convert_split_h_kernel(const float* __restrict__ src,
                                       __half* __restrict__ hi,
                                       __half* __restrict__ lo, int n4) {
    int i = blockIdx.x * blockDim.x + threadIdx.x;
    if (i >= n4) return;
    float4 v = ((const float4*)src)[i];
    uint32_t h0, l0, h1, l1;
    packsplit2h(v.x, v.y, h0, l0);
    packsplit2h(v.z, v.w, h1, l1);
    ((uint32_t*)hi)[2 * i] = h0; ((uint32_t*)hi)[2 * i + 1] = h1;
    ((uint32_t*)lo)[2 * i] = l0; ((uint32_t*)lo)[2 * i + 1] = l1;
}

// ---------------- fused x split-convert + block mean -------------------------
__global__ void x_convert_mean_kernel(const float* __restrict__ x) {
    int blk = blockIdx.x;
    int c4  = threadIdx.x;          // 0..127
    const float4* xr = (const float4*)x + (size_t)blk * LBLK * (DIM / 4) + c4;
    float4 acc = make_float4(0.f, 0.f, 0.f, 0.f);
    for (int r = 0; r < LBLK; r++) {
        float4 v = xr[(size_t)r * (DIM / 4)];
        uint32_t h0, l0, h1, l1;
        packsplit2h(v.x, v.y, h0, l0);
        packsplit2h(v.z, v.w, h1, l1);
        size_t base = ((size_t)(blk * LBLK + r) * DIM) / 2 + c4 * 2;
        ((uint32_t*)g_xh)[base] = h0; ((uint32_t*)g_xh)[base + 1] = h1;
        ((uint32_t*)g_xl)[base] = l0; ((uint32_t*)g_xl)[base + 1] = l1;
        acc.x += v.x; acc.y += v.y; acc.z += v.z; acc.w += v.w;
    }
    const float s = 1.f / 64.f;
    acc.x *= s; acc.y *= s; acc.z *= s; acc.w *= s;
    uint32_t h0, l0, h1, l1;
    packsplit2h(acc.x, acc.y, h0, l0);
    packsplit2h(acc.z, acc.w, h1, l1);
    size_t base = ((size_t)(MTOK + blk) * DIM) / 2 + c4 * 2;
    ((uint32_t*)g_xh)[base] = h0; ((uint32_t*)g_xh)[base + 1] = h1;
    ((uint32_t*)g_xl)[base] = l0; ((uint32_t*)g_xl)[base + 1] = l1;
}

// ---------------- HMMA GEMM: 128x128 tile, 256 threads, 2 CTAs/SM ------------
// NPROD==2: A split (Ah,Al), W single.  NPROD==3: both split (AhWh+AhWl+AlWh).
// MODE==0: C fp32 + bias.  MODE==1: split fp16 (Ch, Cl) + bias.
#define SROW 40
#define T_BYTES (128 * SROW * 2)            // 10240 per 128-row array

template<int NPROD, int MODE>
__global__ __launch_bounds__(256, 2) void gemm_hmma(
    const __half* __restrict__ Ah, const __half* __restrict__ Al,
    const __half* __restrict__ Wh, const __half* __restrict__ Wl,
    const float* __restrict__ bias, float* __restrict__ C,
    __half* __restrict__ Ch, __half* __restrict__ Cl, int Nout)
{
    constexpr int NW = NPROD - 1;                 // W arrays
    constexpr int BUFSZ = (2 + NW) * T_BYTES;

    extern __shared__ char smc[];
    const uint32_t sbase = smem_u32(smc);
    const int tid = threadIdx.x, wid = tid >> 5, lane = tid & 31;
    const int tN = blockIdx.x, tM = blockIdx.y;
    const int wm = wid & 3, wn = wid >> 2;        // 4m x 2n, warp 32x64

    const size_t arow0 = (size_t)tM * 128;
    const size_t wrow0 = (size_t)tN * 128;

    auto load_slab = [&](int s, int buf) {
        uint32_t sb = sbase + buf * BUFSZ;
#pragma unroll
        for (int i = 0; i < 2; i++) {
            int c = tid + 256 * i;                // 512 chunks per array
            int row = c >> 2, q = c & 3;
            uint32_t soff = row * (SROW * 2) + q * 16;
            size_t goff = (size_t)row * GK + s * 32 + q * 8;
            cp_async16(sb + soff, Ah + arow0 * GK + goff);
            cp_async16(sb + T_BYTES + soff, Al + arow0 * GK + goff);
            cp_async16(sb + 2 * T_BYTES + soff, Wh + wrow0 * GK + goff);
            if (NPROD == 3)
                cp_async16(sb + 3 * T_BYTES + soff, Wl + wrow0 * GK + goff);
        }
        CP_COMMIT();
    };

    float acc[2][8][4];
#pragma unroll
    for (int mi = 0; mi < 2; mi++)
#pragma unroll
        for (int ni = 0; ni < 8; ni++)
#pragma unroll
            for (int j = 0; j < 4; j++) acc[mi][ni][j] = 0.f;

    const int a_row = lane & 15, a_kq = lane >> 4;
    const int b_row = (lane & 7) + ((lane >> 4) << 3);
    const int b_kh = (lane >> 3) & 1;

    load_slab(0, 0);
    for (int s = 0; s < 16; s++) {
        if (s + 1 < 16) { load_slab(s + 1, (s + 1) & 1); CP_WAIT(1); }
        else            { CP_WAIT(0); }
        __syncthreads();

        const uint32_t sb = sbase + (s & 1) * BUFSZ;
#pragma unroll
        for (int kk = 0; kk < 2; kk++) {
            uint32_t af[2][2][4];
#pragma unroll
            for (int p = 0; p < 2; p++)
#pragma unroll
                for (int mi = 0; mi < 2; mi++) {
                    uint32_t addr = sb + p * T_BYTES +
                        (wm * 32 + mi * 16 + a_row) * (SROW * 2) +
                        (kk * 16 + a_kq * 8) * 2;
                    ldsm4(af[p][mi], addr);
                }
            uint32_t bf[NW][8][2];
#pragma unroll
            for (int p = 0; p < NW; p++)
#pragma unroll
                for (int j = 0; j < 4; j++) {
                    uint32_t addr = sb + (2 + p) * T_BYTES +
                        (wn * 64 + j * 16 + b_row) * (SROW * 2) +
                        (kk * 16 + b_kh * 8) * 2;
                    uint32_t r[4];
                    ldsm4(r, addr);
                    bf[p][2 * j][0] = r[0]; bf[p][2 * j][1] = r[1];
                    bf[p][2 * j + 1][0] = r[2]; bf[p][2 * j + 1][1] = r[3];
                }
#pragma unroll
            for (int mi = 0; mi < 2; mi++)
#pragma unroll
                for (int ni = 0; ni < 8; ni++) {
                    mma16816h(acc[mi][ni], af[0][mi], bf[0][ni][0], bf[0][ni][1]);
                    if (NPROD == 3)
                        mma16816h(acc[mi][ni], af[0][mi], bf[1][ni][0], bf[1][ni][1]);
                    mma16816h(acc[mi][ni], af[1][mi], bf[0][ni][0], bf[0][ni][1]);
                }
        }
        __syncthreads();
    }

    const int r4 = lane >> 2, c2 = (lane & 3) * 2;
#pragma unroll
    for (int mi = 0; mi < 2; mi++) {
        int row = tM * 128 + wm * 32 + mi * 16 + r4;
#pragma unroll
        for (int ni = 0; ni < 8; ni++) {
            int col = tN * 128 + wn * 64 + ni * 8 + c2;
            float2 bv = *(const float2*)(bias + col);
            float o00 = acc[mi][ni][0] + bv.x, o01 = acc[mi][ni][1] + bv.y;
            float o10 = acc[mi][ni][2] + bv.x, o11 = acc[mi][ni][3] + bv.y;
            if (MODE == 0) {
                *(float2*)(C + (size_t)row * Nout + col) = make_float2(o00, o01);
                *(float2*)(C + (size_t)(row + 8) * Nout + col) = make_float2(o10, o11);
            } else {
                uint32_t hi, lo;
                size_t idx0 = ((size_t)row * Nout + col) >> 1;
                packsplit2h(o00, o01, hi, lo);
                ((uint32_t*)Ch)[idx0] = hi; ((uint32_t*)Cl)[idx0] = lo;
                size_t idx1 = ((size_t)(row + 8) * Nout + col) >> 1;
                packsplit2h(o10, o11, hi, lo);
                ((uint32_t*)Ch)[idx1] = hi; ((uint32_t*)Cl)[idx1] = lo;
            }
        }
    }
}

// ---------------- HMMA attention per (head, block) ---------------------------
#define QH_OFF  0
#define QL_OFF  (64 * 72)
#define KH_OFF  (QL_OFF + 64 * 72)
#define KL_OFF  (KH_OFF + 80 * 72)
#define VH_OFF  (KL_OFF + 80 * 72)
#define VL_OFF  (VH_OFF + 80 * 72)
#define ATTN_SMEM ((VL_OFF + 80 * 72) * 2)   // 64512 B

__global__ __launch_bounds__(128, 3) void attn_kernel(
    const float* __restrict__ edge, const int* __restrict__ mask,
    const float* __restrict__ eg_w, const float* __restrict__ eg_b)
{
    extern __shared__ __half sma[];
    const uint32_t sb32 = smem_u32(sma);
    const int h = blockIdx.x, blk = blockIdx.y;
    const int tid = threadIdx.x, wid = tid >> 5, lane = tid & 31;

    for (int i = tid; i < 540; i += 128) {
        ((uint32_t*)&sma[KH_OFF + 65 * 72])[i] = 0u;
        ((uint32_t*)&sma[KL_OFF + 65 * 72])[i] = 0u;
        ((uint32_t*)&sma[VH_OFF + 65 * 72])[i] = 0u;
        ((uint32_t*)&sma[VL_OFF + 65 * 72])[i] = 0u;
    }

    for (int c = tid; c < 64 * 16; c += 128) {
        int r = c >> 4, p = c & 15;
        size_t g = (size_t)(blk * 64 + r) * QKVN + h * 64 + p * 4;
        *(uint2*)&sma[QH_OFF + r * 72 + p * 4] = *(const uint2*)&g_yh[g];
        *(uint2*)&sma[QL_OFF + r * 72 + p * 4] = *(const uint2*)&g_yl[g];
    }
    for (int c = tid; c < 65 * 16; c += 128) {
        int r = c >> 4, p = c & 15;
        size_t row = (r < 64) ? (size_t)(blk * 64 + r) : (size_t)(MTOK + blk);
        size_t gk = row * QKVN + DIM + h * 64 + p * 4;
        size_t gv = row * QKVN + 2 * DIM + h * 64 + p * 4;
        *(uint2*)&sma[KH_OFF + r * 72 + p * 4] = *(const uint2*)&g_yh[gk];
        *(uint2*)&sma[KL_OFF + r * 72 + p * 4] = *(const uint2*)&g_yl[gk];
        *(uint2*)&sma[VH_OFF + r * 72 + p * 4] = *(const uint2*)&g_yh[gv];
        *(uint2*)&sma[VL_OFF + r * 72 + p * 4] = *(const uint2*)&g_yl[gv];
    }
    __syncthreads();

    const int q0 = wid * 16;
    const int a_row = lane & 15, a_k8 = (lane >> 4) * 8;
    const int b_row = (lane & 7) + ((lane >> 4) << 3);
    const int b_k8 = ((lane >> 3) & 1) * 8;

    float acc[9][4];
#pragma unroll
    for (int j = 0; j < 9; j++)
#pragma unroll
        for (int i = 0; i < 4; i++) acc[j][i] = 0.f;

#pragma unroll
    for (int kt = 0; kt < 4; kt++) {
        uint32_t ah4[4], al4[4];
        ldsm4(ah4, sb32 + (QH_OFF + (q0 + a_row) * 72 + kt * 16 + a_k8) * 2);
        ldsm4(al4, sb32 + (QL_OFF + (q0 + a_row) * 72 + kt * 16 + a_k8) * 2);
#pragma unroll
        for (int t5 = 0; t5 < 5; t5++) {
            uint32_t bh4[4], bl4[4];
            ldsm4(bh4, sb32 + (KH_OFF + (t5 * 16 + b_row) * 72 + kt * 16 + b_k8) * 2);
            ldsm4(bl4, sb32 + (KL_OFF + (t5 * 16 + b_row) * 72 + kt * 16 + b_k8) * 2);
            mma16816h(acc[2 * t5], ah4, bh4[0], bh4[1]);
            mma16816h(acc[2 * t5], ah4, bl4[0], bl4[1]);
            mma16816h(acc[2 * t5], al4, bh4[0], bh4[1]);
            if (t5 < 4) {
                mma16816h(acc[2 * t5 + 1], ah4, bh4[2], bh4[3]);
                mma16816h(acc[2 * t5 + 1], ah4, bl4[2], bl4[3]);
                mma16816h(acc[2 * t5 + 1], al4, bh4[2], bh4[3]);
            }
        }
    }

    const int r4 = lane >> 2, c2b = (lane & 3) * 2;
    const float w0 = eg_w[h * 4 + 0], w1 = eg_w[h * 4 + 1];
    const float w2 = eg_w[h * 4 + 2], w3 = eg_w[h * 4 + 3];
    const float bhh = eg_b[h];
    const float lewd = w3 + bhh;
    const size_t ebase = (size_t)blk * 64 * KEYS;

    float lewf[9][2][2];
    float mx0 = -1e30f, mx1 = -1e30f;
#pragma unroll
    for (int j = 0; j < 9; j++) {
#pragma unroll
        for (int half = 0; half < 2; half++) {
            const int q = q0 + r4 + half * 8;
#pragma unroll
            for (int e = 0; e < 2; e++) {
                const int k = j * 8 + c2b + e;
                float s = acc[j][half * 2 + e];
                float sc, lw;
                if (k > 64) { sc = -1e30f; lw = 0.f; }
                else if (k == 64) { sc = s * 0.125f + 1.f; lw = lewd; }
                else {
                    int m = mask[ebase + (size_t)q * KEYS + k];
                    float4 ev = *(const float4*)(edge + (ebase + (size_t)q * KEYS + k) * 4);
                    float b;
                    if (k == q) { b = 1.f; lw = lewd; }
                    else { b = ev.w; lw = ev.x * w0 + ev.y * w1 + ev.z * w2 + ev.w * w3 + bhh; }
                    sc = s * 0.125f + b;
                    if (m == 0) { sc = -1e30f; lw = 0.f; }
                }
                acc[j][half * 2 + e] = sc;
                lewf[j][half][e] = lw;
                if (half == 0) mx0 = fmaxf(mx0, sc); else mx1 = fmaxf(mx1, sc);
            }
        }
    }
    mx0 = fmaxf(mx0, __shfl_xor_sync(0xffffffffu, mx0, 1));
    mx0 = fmaxf(mx0, __shfl_xor_sync(0xffffffffu, mx0, 2));
    mx1 = fmaxf(mx1, __shfl_xor_sync(0xffffffffu, mx1, 1));
    mx1 = fmaxf(mx1, __shfl_xor_sync(0xffffffffu, mx1, 2));

    float sum0 = 0.f, sum1 = 0.f;
#pragma unroll
    for (int j = 0; j < 9; j++) {
        float e0 = __expf(acc[j][0] - mx0); acc[j][0] = e0; sum0 += e0;
        float e1 = __expf(acc[j][1] - mx0); acc[j][1] = e1; sum0 += e1;
        float e2 = __expf(acc[j][2] - mx1); acc[j][2] = e2; sum1 += e2;
        float e3 = __expf(acc[j][3] - mx1); acc[j][3] = e3; sum1 += e3;
    }
    sum0 += __shfl_xor_sync(0xffffffffu, sum0, 1);
    sum0 += __shfl_xor_sync(0xffffffffu, sum0, 2);
    sum1 += __shfl_xor_sync(0xffffffffu, sum1, 1);
    sum1 += __shfl_xor_sync(0xffffffffu, sum1, 2);
    const float inv0 = 1.f / sum0, inv1 = 1.f / sum1;

    uint32_t cah[5][4], cal[5][4];
#pragma unroll
    for (int kt = 0; kt < 5; kt++) {
#pragma unroll
        for (int jj = 0; jj < 2; jj++) {
            const int j = 2 * kt + jj;
#pragma unroll
            for (int half = 0; half < 2; half++) {
                if (j < 9) {
                    const float iv = half ? inv1 : inv0;
                    float c0 = acc[j][half * 2 + 0] * iv + lewf[j][half][0];
                    float c1 = acc[j][half * 2 + 1] * iv + lewf[j][half][1];
                    packsplit2h(c0, c1, cah[kt][jj * 2 + half], cal[kt][jj * 2 + half]);
                } else {
                    cah[kt][jj * 2 + half] = 0u;
                    cal[kt][jj * 2 + half] = 0u;
                }
            }
        }
    }

    float out[8][4];
#pragma unroll
    for (int n = 0; n < 8; n++)
#pragma unroll
        for (int i = 0; i < 4; i++) out[n][i] = 0.f;

#pragma unroll
    for (int kt = 0; kt < 5; kt++) {
#pragma unroll
        for (int g = 0; g < 4; g++) {
            uint32_t vh4[4], vl4[4];
            uint32_t adr = (kt * 16 + (lane & 15)) * 72 + g * 16 + ((lane >> 4) * 8);
            ldsm4t(vh4, sb32 + (VH_OFF + adr) * 2);
            ldsm4t(vl4, sb32 + (VL_OFF + adr) * 2);
            mma16816h(out[2 * g],     cah[kt], vh4[0], vh4[1]);
            mma16816h(out[2 * g],     cah[kt], vl4[0], vl4[1]);
            mma16816h(out[2 * g],     cal[kt], vh4[0], vh4[1]);
            mma16816h(out[2 * g + 1], cah[kt], vh4[2], vh4[3]);
            mma16816h(out[2 * g + 1], cah[kt], vl4[2], vl4[3]);
            mma16816h(out[2 * g + 1], cal[kt], vh4[2], vh4[3]);
        }
    }

#pragma unroll
    for (int n = 0; n < 8; n++) {
        const int d = n * 8 + c2b;
#pragma unroll
        for (int half = 0; half < 2; half++) {
            const int q = q0 + r4 + half * 8;
            const size_t idx = ((size_t)(blk * 64 + q) * DIM + h * 64 + d) >> 1;
            uint32_t hi, lo;
            packsplit2h(out[n][half * 2], out[n][half * 2 + 1], hi, lo);
            ((uint32_t*)g_aoh)[idx] = hi;
            ((uint32_t*)g_aol)[idx] = lo;
        }
    }
}

// ---------------- host -------------------------------------------------------
extern "C" void kernel_launch(void* const* d_in, const int* in_sizes, int n_in,
                              void* d_out, int out_size)
{
    const float* x      = (const float*)d_in[0];
    const int*   mask   = (const int*)  d_in[1];
    const float* edge   = (const float*)d_in[2];
    const float* qkv_w  = (const float*)d_in[3];
    const float* qkv_b  = (const float*)d_in[4];
    const float* proj_w = (const float*)d_in[5];
    const float* proj_b = (const float*)d_in[6];
    const float* eg_w   = (const float*)d_in[7];
    const float* eg_b   = (const float*)d_in[8];
    float* out = (float*)d_out;

    void *p_xh, *p_xl, *p_yh, *p_yl, *p_aoh, *p_aol, *p_qw, *p_pwh, *p_pwl;
    cudaGetSymbolAddress(&p_xh, g_xh);   cudaGetSymbolAddress(&p_xl, g_xl);
    cudaGetSymbolAddress(&p_yh, g_yh);   cudaGetSymbolAddress(&p_yl, g_yl);
    cudaGetSymbolAddress(&p_aoh, g_aoh); cudaGetSymbolAddress(&p_aol, g_aol);
    cudaGetSymbolAddress(&p_qw, g_qw);
    cudaGetSymbolAddress(&p_pwh, g_pwh); cudaGetSymbolAddress(&p_pwl, g_pwl);

    const int qkv_smem  = 2 * 3 * T_BYTES;    // 61440
    const int proj_smem = 2 * 4 * T_BYTES;    // 81920
    cudaFuncSetAttribute(gemm_hmma<2, 1>, cudaFuncAttributeMaxDynamicSharedMemorySize, qkv_smem);
    cudaFuncSetAttribute(gemm_hmma<3, 0>, cudaFuncAttributeMaxDynamicSharedMemorySize, proj_smem);
    cudaFuncSetAttribute(attn_kernel, cudaFuncAttributeMaxDynamicSharedMemorySize, ATTN_SMEM);

    x_convert_mean_kernel<<<NBLK, 128>>>(x);
    convert_half_kernel<<<(QKVN * DIM / 4 + 255) / 256, 256>>>(
        qkv_w, (__half*)p_qw, QKVN * DIM / 4);
    convert_split_h_kernel<<<(DIM * DIM / 4 + 255) / 256, 256>>>(
        proj_w, (__half*)p_pwh, (__half*)p_pwl, DIM * DIM / 4);

    dim3 g1(QKVN / 128, MAUG / 128);          // (12, 520)
    gemm_hmma<2, 1><<<g1, 256, qkv_smem>>>(
        (const __half*)p_xh, (const __half*)p_xl,
        (const __half*)p_qw, nullptr,
        qkv_b, nullptr, (__half*)p_yh, (__half*)p_yl, QKVN);

    dim3 g2(NHEAD, NBLK);
    attn_kernel<<<g2, 128, ATTN_SMEM>>>(edge, mask, eg_w, eg_b);

    dim3 g3(DIM / 128, MTOK / 128);           // (4, 512)
    gemm_hmma<3, 0><<<g3, 256, proj_smem>>>(
        (const __half*)p_aoh, (const __half*)p_aol,
        (const __half*)p_pwh, (const __half*)p_pwl,
        proj_b, out, nullptr, nullptr, DIM);
}

// round 12
// speedup vs baseline: 1.4122x; 1.0454x over previous
#include <cuda_runtime.h>
#include <cuda_fp16.h>
#include <cstdint>
#include <math.h>

#define DIM   512
#define LBLK  64
#define NHEAD 8
#define KEYS  65
#define BB    2
#define NTOK  32768
#define NBPB  512
#define NBLK  (BB*NBPB)           // 1024
#define MTOK  (BB*NTOK)           // 65536
#define MAUG  (MTOK+NBLK)         // 66560
#define QKVN  (3*DIM)             // 1536
#define GK    512

// ---------------- scratch ----------------------------------------------------
__device__ __half g_xh[(size_t)MAUG * DIM];
__device__ __half g_xl[(size_t)MAUG * DIM];
__device__ __half g_yh[(size_t)MAUG * QKVN];
__device__ __half g_yl[(size_t)MAUG * QKVN];
__device__ __half g_aoh[(size_t)MTOK * DIM];
__device__ __half g_aol[(size_t)MTOK * DIM];
__device__ __half g_qw[(size_t)QKVN * DIM];
__device__ __half g_pwh[(size_t)DIM * DIM];
__device__ __half g_pwl[(size_t)DIM * DIM];

// ---------------- helpers ----------------------------------------------------
__device__ __forceinline__ uint32_t smem_u32(const void* p) {
    uint32_t a;
    asm("{ .reg .u64 t; cvta.to.shared.u64 t, %1; cvt.u32.u64 %0, t; }"
        : "=r"(a) : "l"(p));
    return a;
}
__device__ __forceinline__ void cp_async16(uint32_t dst, const void* src) {
    asm volatile("cp.async.cg.shared.global [%0], [%1], 16;"
                 :: "r"(dst), "l"(src) : "memory");
}
#define CP_COMMIT() asm volatile("cp.async.commit_group;" ::: "memory")
#define CP_WAIT(n)  asm volatile("cp.async.wait_group %0;" :: "n"(n) : "memory")

__device__ __forceinline__ void ldsm4(uint32_t (&r)[4], uint32_t addr) {
    asm volatile("ldmatrix.sync.aligned.m8n8.x4.shared.b16 {%0,%1,%2,%3}, [%4];"
                 : "=r"(r[0]), "=r"(r[1]), "=r"(r[2]), "=r"(r[3]) : "r"(addr));
}
__device__ __forceinline__ void ldsm4t(uint32_t (&r)[4], uint32_t addr) {
    asm volatile("ldmatrix.sync.aligned.m8n8.x4.trans.shared.b16 {%0,%1,%2,%3}, [%4];"
                 : "=r"(r[0]), "=r"(r[1]), "=r"(r[2]), "=r"(r[3]) : "r"(addr));
}
__device__ __forceinline__ void mma16816h(float (&d)[4], const uint32_t (&a)[4],
                                          const uint32_t b0, const uint32_t b1) {
    asm volatile(
        "mma.sync.aligned.m16n8k16.row.col.f32.f16.f16.f32 "
        "{%0,%1,%2,%3}, {%4,%5,%6,%7}, {%8,%9}, {%0,%1,%2,%3};"
        : "+f"(d[0]), "+f"(d[1]), "+f"(d[2]), "+f"(d[3])
        : "r"(a[0]), "r"(a[1]), "r"(a[2]), "r"(a[3]), "r"(b0), "r"(b1));
}
__device__ __forceinline__ void packsplit2h(float c0, float c1,
                                            uint32_t& hi, uint32_t& lo) {
    __half2 h = __floats2half2_rn(c0, c1);
    float2 hf = __half22float2(h);
    __half2 l = __floats2half2_rn(c0 - hf.x, c1 - hf.y);
    hi = *reinterpret_cast<uint32_t*>(&h);
    lo = *reinterpret_cast<uint32_t*>(&l);
}

// ---------------- weight converts -------------------------------------------
__global__ void convert_half_kernel(const float* __restrict__ src,
                                    __half* __restrict__ dst, int n4) {
    int i = blockIdx.x * blockDim.x + threadIdx.x;
    if (i >= n4) return;
    float4 v = ((const float4*)src)[i];
    ((__half2*)dst)[2 * i]     = __floats2half2_rn(v.x, v.y);
    ((__half2*)dst)[2 * i + 1] = __floats2half2_rn(v.z, v.w);
}
__global__ void convert_split_h_kernel(const float* __restrict__ src,
                                       __half* __restrict__ hi,
                                       __half* __restrict__ lo, int n4) {
    int i = blockIdx.x * blockDim.x + threadIdx.x;
    if (i >= n4) return;
    float4 v = ((const float4*)src)[i];
    uint32_t h0, l0, h1, l1;
    packsplit2h(v.x, v.y, h0, l0);
    packsplit2h(v.z, v.w, h1, l1);
    ((uint32_t*)hi)[2 * i] = h0; ((uint32_t*)hi)[2 * i + 1] = h1;
    ((uint32_t*)lo)[2 * i] = l0; ((uint32_t*)lo)[2 * i + 1] = l1;
}

// ---------------- fused x split-convert + block mean -------------------------
__global__ void x_convert_mean_kernel(const float* __restrict__ x) {
    int blk = blockIdx.x;
    int c4  = threadIdx.x;          // 0..127
    const float4* xr = (const float4*)x + (size_t)blk * LBLK * (DIM / 4) + c4;
    float4 acc = make_float4(0.f, 0.f, 0.f, 0.f);
    for (int r = 0; r < LBLK; r++) {
        float4 v = xr[(size_t)r * (DIM / 4)];
        uint32_t h0, l0, h1, l1;
        packsplit2h(v.x, v.y, h0, l0);
        packsplit2h(v.z, v.w, h1, l1);
        size_t base = ((size_t)(blk * LBLK + r) * DIM) / 2 + c4 * 2;
        ((uint32_t*)g_xh)[base] = h0; ((uint32_t*)g_xh)[base + 1] = h1;
        ((uint32_t*)g_xl)[base] = l0; ((uint32_t*)g_xl)[base + 1] = l1;
        acc.x += v.x; acc.y += v.y; acc.z += v.z; acc.w += v.w;
    }
    const float s = 1.f / 64.f;
    acc.x *= s; acc.y *= s; acc.z *= s; acc.w *= s;
    uint32_t h0, l0, h1, l1;
    packsplit2h(acc.x, acc.y, h0, l0);
    packsplit2h(acc.z, acc.w, h1, l1);
    size_t base = ((size_t)(MTOK + blk) * DIM) / 2 + c4 * 2;
    ((uint32_t*)g_xh)[base] = h0; ((uint32_t*)g_xh)[base + 1] = h1;
    ((uint32_t*)g_xl)[base] = l0; ((uint32_t*)g_xl)[base + 1] = l1;
}

// ---------------- HMMA GEMM: 128x128 tile, 256 threads, 2 CTAs/SM ------------
// NPROD==2: A split, W single.  NPROD==3: both split (AhWh+AhWl+AlWh).
// MODE==0: C fp32 + bias.  MODE==1: split fp16 (Ch, Cl) + bias.
// BK: K-slab depth (32 or 64). Single __syncthreads per slab.
template<int NPROD, int MODE, int BK>
__global__ __launch_bounds__(256, 2) void gemm_hmma(
    const __half* __restrict__ Ah, const __half* __restrict__ Al,
    const __half* __restrict__ Wh, const __half* __restrict__ Wl,
    const float* __restrict__ bias, float* __restrict__ C,
    __half* __restrict__ Ch, __half* __restrict__ Cl, int Nout)
{
    constexpr int NW = NPROD - 1;             // W arrays
    constexpr int SR = BK + 8;                // halfs per smem row
    constexpr int TB = 128 * SR * 2;          // bytes per 128-row array
    constexpr int BUFSZ = (2 + NW) * TB;
    constexpr int NSLAB = GK / BK;
    constexpr int CPR = BK / 8;               // 16B chunks per row
    constexpr int CPT = 128 * CPR / 256;      // chunks per thread per array

    extern __shared__ char smc[];
    const uint32_t sbase = smem_u32(smc);
    const int tid = threadIdx.x, wid = tid >> 5, lane = tid & 31;
    const int tN = blockIdx.x, tM = blockIdx.y;
    const int wm = wid & 3, wn = wid >> 2;    // 4m x 2n, warp 32x64

    const size_t arow0 = (size_t)tM * 128;
    const size_t wrow0 = (size_t)tN * 128;

    auto load_slab = [&](int s, int buf) {
        uint32_t sb = sbase + buf * BUFSZ;
#pragma unroll
        for (int i = 0; i < CPT; i++) {
            int c = tid + 256 * i;
            int row = c / CPR, q = c % CPR;
            uint32_t soff = row * (SR * 2) + q * 16;
            size_t goff = (size_t)row * GK + s * BK + q * 8;
            cp_async16(sb + soff, Ah + arow0 * GK + goff);
            cp_async16(sb + TB + soff, Al + arow0 * GK + goff);
            cp_async16(sb + 2 * TB + soff, Wh + wrow0 * GK + goff);
            if (NPROD == 3)
                cp_async16(sb + 3 * TB + soff, Wl + wrow0 * GK + goff);
        }
        CP_COMMIT();
    };

    float acc[2][8][4];
#pragma unroll
    for (int mi = 0; mi < 2; mi++)
#pragma unroll
        for (int ni = 0; ni < 8; ni++)
#pragma unroll
            for (int j = 0; j < 4; j++) acc[mi][ni][j] = 0.f;

    const int a_row = lane & 15, a_kq = lane >> 4;
    const int b_row = (lane & 7) + ((lane >> 4) << 3);
    const int b_kh = (lane >> 3) & 1;

    load_slab(0, 0);
    for (int s = 0; s < NSLAB; s++) {
        CP_WAIT(0);
        __syncthreads();
        // issue next slab's loads into the other buffer — its previous reader
        // (compute of slab s-1) is complete for all warps after the sync above.
        if (s + 1 < NSLAB) load_slab(s + 1, (s + 1) & 1);

        const uint32_t sb = sbase + (s & 1) * BUFSZ;
#pragma unroll
        for (int kk = 0; kk < BK / 16; kk++) {
            uint32_t af[2][2][4];
#pragma unroll
            for (int p = 0; p < 2; p++)
#pragma unroll
                for (int mi = 0; mi < 2; mi++) {
                    uint32_t addr = sb + p * TB +
                        (wm * 32 + mi * 16 + a_row) * (SR * 2) +
                        (kk * 16 + a_kq * 8) * 2;
                    ldsm4(af[p][mi], addr);
                }
            uint32_t bf[NW][8][2];
#pragma unroll
            for (int p = 0; p < NW; p++)
#pragma unroll
                for (int j = 0; j < 4; j++) {
                    uint32_t addr = sb + (2 + p) * TB +
                        (wn * 64 + j * 16 + b_row) * (SR * 2) +
                        (kk * 16 + b_kh * 8) * 2;
                    uint32_t r[4];
                    ldsm4(r, addr);
                    bf[p][2 * j][0] = r[0]; bf[p][2 * j][1] = r[1];
                    bf[p][2 * j + 1][0] = r[2]; bf[p][2 * j + 1][1] = r[3];
                }
#pragma unroll
            for (int mi = 0; mi < 2; mi++)
#pragma unroll
                for (int ni = 0; ni < 8; ni++) {
                    mma16816h(acc[mi][ni], af[0][mi], bf[0][ni][0], bf[0][ni][1]);
                    if (NPROD == 3)
                        mma16816h(acc[mi][ni], af[0][mi], bf[1][ni][0], bf[1][ni][1]);
                    mma16816h(acc[mi][ni], af[1][mi], bf[0][ni][0], bf[0][ni][1]);
                }
        }
    }

    const int r4 = lane >> 2, c2 = (lane & 3) * 2;
#pragma unroll
    for (int mi = 0; mi < 2; mi++) {
        int row = tM * 128 + wm * 32 + mi * 16 + r4;
#pragma unroll
        for (int ni = 0; ni < 8; ni++) {
            int col = tN * 128 + wn * 64 + ni * 8 + c2;
            float2 bv = *(const float2*)(bias + col);
            float o00 = acc[mi][ni][0] + bv.x, o01 = acc[mi][ni][1] + bv.y;
            float o10 = acc[mi][ni][2] + bv.x, o11 = acc[mi][ni][3] + bv.y;
            if (MODE == 0) {
                *(float2*)(C + (size_t)row * Nout + col) = make_float2(o00, o01);
                *(float2*)(C + (size_t)(row + 8) * Nout + col) = make_float2(o10, o11);
            } else {
                uint32_t hi, lo;
                size_t idx0 = ((size_t)row * Nout + col) >> 1;
                packsplit2h(o00, o01, hi, lo);
                ((uint32_t*)Ch)[idx0] = hi; ((uint32_t*)Cl)[idx0] = lo;
                size_t idx1 = ((size_t)(row + 8) * Nout + col) >> 1;
                packsplit2h(o10, o11, hi, lo);
                ((uint32_t*)Ch)[idx1] = hi; ((uint32_t*)Cl)[idx1] = lo;
            }
        }
    }
}

// ---------------- HMMA attention per (head, block) ---------------------------
#define QH_OFF  0
#define QL_OFF  (64 * 72)
#define KH_OFF  (QL_OFF + 64 * 72)
#define KL_OFF  (KH_OFF + 80 * 72)
#define VH_OFF  (KL_OFF + 80 * 72)
#define VL_OFF  (VH_OFF + 80 * 72)
#define ATTN_SMEM ((VL_OFF + 80 * 72) * 2)   // 64512 B

__global__ __launch_bounds__(128, 3) void attn_kernel(
    const float* __restrict__ edge, const int* __restrict__ mask,
    const float* __restrict__ eg_w, const float* __restrict__ eg_b)
{
    extern __shared__ __half sma[];
    const uint32_t sb32 = smem_u32(sma);
    const int h = blockIdx.x, blk = blockIdx.y;
    const int tid = threadIdx.x, wid = tid >> 5, lane = tid & 31;

    for (int i = tid; i < 540; i += 128) {
        ((uint32_t*)&sma[KH_OFF + 65 * 72])[i] = 0u;
        ((uint32_t*)&sma[KL_OFF + 65 * 72])[i] = 0u;
        ((uint32_t*)&sma[VH_OFF + 65 * 72])[i] = 0u;
        ((uint32_t*)&sma[VL_OFF + 65 * 72])[i] = 0u;
    }

    for (int c = tid; c < 64 * 16; c += 128) {
        int r = c >> 4, p = c & 15;
        size_t g = (size_t)(blk * 64 + r) * QKVN + h * 64 + p * 4;
        *(uint2*)&sma[QH_OFF + r * 72 + p * 4] = *(const uint2*)&g_yh[g];
        *(uint2*)&sma[QL_OFF + r * 72 + p * 4] = *(const uint2*)&g_yl[g];
    }
    for (int c = tid; c < 65 * 16; c += 128) {
        int r = c >> 4, p = c & 15;
        size_t row = (r < 64) ? (size_t)(blk * 64 + r) : (size_t)(MTOK + blk);
        size_t gk = row * QKVN + DIM + h * 64 + p * 4;
        size_t gv = row * QKVN + 2 * DIM + h * 64 + p * 4;
        *(uint2*)&sma[KH_OFF + r * 72 + p * 4] = *(const uint2*)&g_yh[gk];
        *(uint2*)&sma[KL_OFF + r * 72 + p * 4] = *(const uint2*)&g_yl[gk];
        *(uint2*)&sma[VH_OFF + r * 72 + p * 4] = *(const uint2*)&g_yh[gv];
        *(uint2*)&sma[VL_OFF + r * 72 + p * 4] = *(const uint2*)&g_yl[gv];
    }
    __syncthreads();

    const int q0 = wid * 16;
    const int a_row = lane & 15, a_k8 = (lane >> 4) * 8;
    const int b_row = (lane & 7) + ((lane >> 4) << 3);
    const int b_k8 = ((lane >> 3) & 1) * 8;

    float acc[9][4];
#pragma unroll
    for (int j = 0; j < 9; j++)
#pragma unroll
        for (int i = 0; i < 4; i++) acc[j][i] = 0.f;

#pragma unroll
    for (int kt = 0; kt < 4; kt++) {
        uint32_t ah4[4], al4[4];
        ldsm4(ah4, sb32 + (QH_OFF + (q0 + a_row) * 72 + kt * 16 + a_k8) * 2);
        ldsm4(al4, sb32 + (QL_OFF + (q0 + a_row) * 72 + kt * 16 + a_k8) * 2);
#pragma unroll
        for (int t5 = 0; t5 < 5; t5++) {
            uint32_t bh4[4], bl4[4];
            ldsm4(bh4, sb32 + (KH_OFF + (t5 * 16 + b_row) * 72 + kt * 16 + b_k8) * 2);
            ldsm4(bl4, sb32 + (KL_OFF + (t5 * 16 + b_row) * 72 + kt * 16 + b_k8) * 2);
            mma16816h(acc[2 * t5], ah4, bh4[0], bh4[1]);
            mma16816h(acc[2 * t5], ah4, bl4[0], bl4[1]);
            mma16816h(acc[2 * t5], al4, bh4[0], bh4[1]);
            if (t5 < 4) {
                mma16816h(acc[2 * t5 + 1], ah4, bh4[2], bh4[3]);
                mma16816h(acc[2 * t5 + 1], ah4, bl4[2], bl4[3]);
                mma16816h(acc[2 * t5 + 1], al4, bh4[2], bh4[3]);
            }
        }
    }

    const int r4 = lane >> 2, c2b = (lane & 3) * 2;
    const float w0 = eg_w[h * 4 + 0], w1 = eg_w[h * 4 + 1];
    const float w2 = eg_w[h * 4 + 2], w3 = eg_w[h * 4 + 3];
    const float bhh = eg_b[h];
    const float lewd = w3 + bhh;
    const size_t ebase = (size_t)blk * 64 * KEYS;

    float lewf[9][2][2];
    float mx0 = -1e30f, mx1 = -1e30f;
#pragma unroll
    for (int j = 0; j < 9; j++) {
#pragma unroll
        for (int half = 0; half < 2; half++) {
            const int q = q0 + r4 + half * 8;
#pragma unroll
            for (int e = 0; e < 2; e++) {
                const int k = j * 8 + c2b + e;
                float s = acc[j][half * 2 + e];
                float sc, lw;
                if (k > 64) { sc = -1e30f; lw = 0.f; }
                else if (k == 64) { sc = s * 0.125f + 1.f; lw = lewd; }
                else {
                    int m = mask[ebase + (size_t)q * KEYS + k];
                    float4 ev = *(const float4*)(edge + (ebase + (size_t)q * KEYS + k) * 4);
                    float b;
                    if (k == q) { b = 1.f; lw = lewd; }
                    else { b = ev.w; lw = ev.x * w0 + ev.y * w1 + ev.z * w2 + ev.w * w3 + bhh; }
                    sc = s * 0.125f + b;
                    if (m == 0) { sc = -1e30f; lw = 0.f; }
                }
                acc[j][half * 2 + e] = sc;
                lewf[j][half][e] = lw;
                if (half == 0) mx0 = fmaxf(mx0, sc); else mx1 = fmaxf(mx1, sc);
            }
        }
    }
    mx0 = fmaxf(mx0, __shfl_xor_sync(0xffffffffu, mx0, 1));
    mx0 = fmaxf(mx0, __shfl_xor_sync(0xffffffffu, mx0, 2));
    mx1 = fmaxf(mx1, __shfl_xor_sync(0xffffffffu, mx1, 1));
    mx1 = fmaxf(mx1, __shfl_xor_sync(0xffffffffu, mx1, 2));

    float sum0 = 0.f, sum1 = 0.f;
#pragma unroll
    for (int j = 0; j < 9; j++) {
        float e0 = __expf(acc[j][0] - mx0); acc[j][0] = e0; sum0 += e0;
        float e1 = __expf(acc[j][1] - mx0); acc[j][1] = e1; sum0 += e1;
        float e2 = __expf(acc[j][2] - mx1); acc[j][2] = e2; sum1 += e2;
        float e3 = __expf(acc[j][3] - mx1); acc[j][3] = e3; sum1 += e3;
    }
    sum0 += __shfl_xor_sync(0xffffffffu, sum0, 1);
    sum0 += __shfl_xor_sync(0xffffffffu, sum0, 2);
    sum1 += __shfl_xor_sync(0xffffffffu, sum1, 1);
    sum1 += __shfl_xor_sync(0xffffffffu, sum1, 2);
    const float inv0 = 1.f / sum0, inv1 = 1.f / sum1;

    uint32_t cah[5][4], cal[5][4];
#pragma unroll
    for (int kt = 0; kt < 5; kt++) {
#pragma unroll
        for (int jj = 0; jj < 2; jj++) {
            const int j = 2 * kt + jj;
#pragma unroll
            for (int half = 0; half < 2; half++) {
                if (j < 9) {
                    const float iv = half ? inv1 : inv0;
                    float c0 = acc[j][half * 2 + 0] * iv + lewf[j][half][0];
                    float c1 = acc[j][half * 2 + 1] * iv + lewf[j][half][1];
                    packsplit2h(c0, c1, cah[kt][jj * 2 + half], cal[kt][jj * 2 + half]);
                } else {
                    cah[kt][jj * 2 + half] = 0u;
                    cal[kt][jj * 2 + half] = 0u;
                }
            }
        }
    }

    float out[8][4];
#pragma unroll
    for (int n = 0; n < 8; n++)
#pragma unroll
        for (int i = 0; i < 4; i++) out[n][i] = 0.f;

#pragma unroll
    for (int kt = 0; kt < 5; kt++) {
#pragma unroll
        for (int g = 0; g < 4; g++) {
            uint32_t vh4[4], vl4[4];
            uint32_t adr = (kt * 16 + (lane & 15)) * 72 + g * 16 + ((lane >> 4) * 8);
            ldsm4t(vh4, sb32 + (VH_OFF + adr) * 2);
            ldsm4t(vl4, sb32 + (VL_OFF + adr) * 2);
            mma16816h(out[2 * g],     cah[kt], vh4[0], vh4[1]);
            mma16816h(out[2 * g],     cah[kt], vl4[0], vl4[1]);
            mma16816h(out[2 * g],     cal[kt], vh4[0], vh4[1]);
            mma16816h(out[2 * g + 1], cah[kt], vh4[2], vh4[3]);
            mma16816h(out[2 * g + 1], cah[kt], vl4[2], vl4[3]);
            mma16816h(out[2 * g + 1], cal[kt], vh4[2], vh4[3]);
        }
    }

#pragma unroll
    for (int n = 0; n < 8; n++) {
        const int d = n * 8 + c2b;
#pragma unroll
        for (int half = 0; half < 2; half++) {
            const int q = q0 + r4 + half * 8;
            const size_t idx = ((size_t)(blk * 64 + q) * DIM + h * 64 + d) >> 1;
            uint32_t hi, lo;
            packsplit2h(out[n][half * 2], out[n][half * 2 + 1], hi, lo);
            ((uint32_t*)g_aoh)[idx] = hi;
            ((uint32_t*)g_aol)[idx] = lo;
        }
    }
}

// ---------------- host -------------------------------------------------------
extern "C" void kernel_launch(void* const* d_in, const int* in_sizes, int n_in,
                              void* d_out, int out_size)
{
    const float* x      = (const float*)d_in[0];
    const int*   mask   = (const int*)  d_in[1];
    const float* edge   = (const float*)d_in[2];
    const float* qkv_w  = (const float*)d_in[3];
    const float* qkv_b  = (const float*)d_in[4];
    const float* proj_w = (const float*)d_in[5];
    const float* proj_b = (const float*)d_in[6];
    const float* eg_w   = (const float*)d_in[7];
    const float* eg_b   = (const float*)d_in[8];
    float* out = (float*)d_out;

    void *p_xh, *p_xl, *p_yh, *p_yl, *p_aoh, *p_aol, *p_qw, *p_pwh, *p_pwl;
    cudaGetSymbolAddress(&p_xh, g_xh);   cudaGetSymbolAddress(&p_xl, g_xl);
    cudaGetSymbolAddress(&p_yh, g_yh);   cudaGetSymbolAddress(&p_yl, g_yl);
    cudaGetSymbolAddress(&p_aoh, g_aoh); cudaGetSymbolAddress(&p_aol, g_aol);
    cudaGetSymbolAddress(&p_qw, g_qw);
    cudaGetSymbolAddress(&p_pwh, g_pwh); cudaGetSymbolAddress(&p_pwl, g_pwl);

    const int qkv_smem  = 2 * 3 * (128 * 72 * 2);    // 110592 (BK=64)
    const int proj_smem = 2 * 4 * (128 * 40 * 2);    // 81920  (BK=32)
    cudaFuncSetAttribute(gemm_hmma<2, 1, 64>, cudaFuncAttributeMaxDynamicSharedMemorySize, qkv_smem);
    cudaFuncSetAttribute(gemm_hmma<3, 0, 32>, cudaFuncAttributeMaxDynamicSharedMemorySize, proj_smem);
    cudaFuncSetAttribute(attn_kernel, cudaFuncAttributeMaxDynamicSharedMemorySize, ATTN_SMEM);

    x_convert_mean_kernel<<<NBLK, 128>>>(x);
    convert_half_kernel<<<(QKVN * DIM / 4 + 255) / 256, 256>>>(
        qkv_w, (__half*)p_qw, QKVN * DIM / 4);
    convert_split_h_kernel<<<(DIM * DIM / 4 + 255) / 256, 256>>>(
        proj_w, (__half*)p_pwh, (__half*)p_pwl, DIM * DIM / 4);

    dim3 g1(QKVN / 128, MAUG / 128);          // (12, 520)
    gemm_hmma<2, 1, 64><<<g1, 256, qkv_smem>>>(
        (const __half*)p_xh, (const __half*)p_xl,
        (const __half*)p_qw, nullptr,
        qkv_b, nullptr, (__half*)p_yh, (__half*)p_yl, QKVN);

    dim3 g2(NHEAD, NBLK);
    attn_kernel<<<g2, 128, ATTN_SMEM>>>(edge, mask, eg_w, eg_b);

    dim3 g3(DIM / 128, MTOK / 128);           // (4, 512)
    gemm_hmma<3, 0, 32><<<g3, 256, proj_smem>>>(
        (const __half*)p_aoh, (const __half*)p_aol,
        (const __half*)p_pwh, (const __half*)p_pwl,
        proj_b, out, nullptr, nullptr, DIM);
}